// round 13
// baseline (speedup 1.0000x reference)
#include <cuda_runtime.h>
#include <cuda_bf16.h>
#include <cuda_fp16.h>
#include <cstdint>

#define NN 20000
#define EE 320000
#define ETOT 340000   // EE + NN self loops
#define NODD 512
#define HIDD 128
#define NLAYERS 3
#define SP 136        // padded bf16 smem row stride (pair kernel A)
#define SPC 72        // padded fp16 smem row stride (k=64 chunks)
#define NB 157        // ceil(NN/128)
#define NSPLIT 10048  // 157*64: row-aligned pipeline split point

// ---------------- static scratch ----------------
__device__ float d_h[NN * HIDD];
__device__ __half d_hf[NN * HIDD];          // h in fp16 (gemm A operand)
__device__ __half d_zh[2 * NN * 512];       // z in fp16, double-buffered by layer parity
__device__ float d_es[NLAYERS * NN * 4];    // per-layer (zeroed once)
__device__ float d_ed[NLAYERS * NN * 4];
__device__ int   d_cnt[NN];
__device__ int   d_cur[NN];
__device__ int   d_off[NN + 1];
__device__ int   d_csr[ETOT];
__device__ int   d_blk[NB + 8];
__device__ float d_P[NODD * HIDD];
__device__ float d_Q[NODD * HIDD];
__device__ __half d_wtf[NLAYERS * 512 * 128];            // gat_W transposed fp16 [l][n][k]
__device__ __nv_bfloat16 d_w2t_hi[128 * 128];            // sW2 transposed (pair: bf16x3)
__device__ __nv_bfloat16 d_w2t_lo[128 * 128];

__device__ __forceinline__ void bsplit(float v, __nv_bfloat16& hi, __nv_bfloat16& lo) {
    hi = __float2bfloat16(v);
    lo = __float2bfloat16(v - __bfloat162float(hi));
}

__device__ __forceinline__ void mma_bf16(float* c, uint32_t a0, uint32_t a1, uint32_t a2,
                                         uint32_t a3, uint32_t b0, uint32_t b1) {
    asm volatile(
        "mma.sync.aligned.m16n8k16.row.col.f32.bf16.bf16.f32 "
        "{%0,%1,%2,%3}, {%4,%5,%6,%7}, {%8,%9}, {%0,%1,%2,%3};\n"
        : "+f"(c[0]), "+f"(c[1]), "+f"(c[2]), "+f"(c[3])
        : "r"(a0), "r"(a1), "r"(a2), "r"(a3), "r"(b0), "r"(b1));
}

__device__ __forceinline__ void mma_f16(float* c, uint32_t a0, uint32_t a1, uint32_t a2,
                                        uint32_t a3, uint32_t b0, uint32_t b1) {
    asm volatile(
        "mma.sync.aligned.m16n8k16.row.col.f32.f16.f16.f32 "
        "{%0,%1,%2,%3}, {%4,%5,%6,%7}, {%8,%9}, {%0,%1,%2,%3};\n"
        : "+f"(c[0]), "+f"(c[1]), "+f"(c[2]), "+f"(c[3])
        : "r"(a0), "r"(a1), "r"(a2), "r"(a3), "r"(b0), "r"(b1));
}

__device__ __forceinline__ void ldmA(uint32_t* a, uint32_t saddr) {
    asm volatile("ldmatrix.sync.aligned.m8n8.x4.shared.b16 {%0,%1,%2,%3}, [%4];"
                 : "=r"(a[0]), "=r"(a[1]), "=r"(a[2]), "=r"(a[3]) : "r"(saddr));
}
__device__ __forceinline__ void ldmB2(uint32_t& b0, uint32_t& b1, uint32_t saddr) {
    asm volatile("ldmatrix.sync.aligned.m8n8.x2.shared.b16 {%0,%1}, [%2];"
                 : "=r"(b0), "=r"(b1) : "r"(saddr));
}

// ---------------- prologue: prep_w + prep_w2 + node_proj + all zeroing ----------------
#define PRO_W   1536
#define PRO_W2  128
#define PRO_NP  20000
#define PRO_Z   1875
#define PRO_GRID (PRO_W + PRO_W2 + PRO_NP + PRO_Z)

__global__ void k_prologue(const float* __restrict__ gw,
                           const float* __restrict__ w2,
                           const float* __restrict__ x,
                           const float* __restrict__ nW,
                           const float* __restrict__ nb) {
    int b = blockIdx.x, t = threadIdx.x;
    if (b < PRO_W) {
        int l = b >> 9, n = b & 511;
        d_wtf[(l * 512 + n) * 128 + t] = __float2half(gw[(l * 128 + t) * 512 + n]);
    } else if (b < PRO_W + PRO_W2) {
        int n = b - PRO_W;
        float v = w2[t * 128 + n];
        __nv_bfloat16 hi, lo; bsplit(v, hi, lo);
        d_w2t_hi[n * 128 + t] = hi;
        d_w2t_lo[n * 128 + t] = lo;
    } else if (b < PRO_W + PRO_W2 + PRO_NP) {
        int n = b - PRO_W - PRO_W2;
        float acc = nb[t];
#pragma unroll
        for (int k = 0; k < 5; k++) acc += x[n * 5 + k] * nW[k * HIDD + t];
        acc = fmaxf(acc, 0.f);
        d_h[n * HIDD + t] = acc;
        d_hf[n * HIDD + t] = __float2half(acc);
    } else {
        int i = (b - PRO_W - PRO_W2 - PRO_NP) * 128 + t;
        if (i < NN) d_cnt[i] = 0;
        if (i < NLAYERS * NN * 4) { d_es[i] = 0.f; d_ed[i] = 0.f; }
    }
}

// ---------------- CSR build ----------------
__global__ void k_hist(const int* __restrict__ ei) {
    int e = blockIdx.x * blockDim.x + threadIdx.x;
    if (e >= ETOT) return;
    int d = (e < EE) ? ei[EE + e] : (e - EE);
    atomicAdd(&d_cnt[d], 1);
}
__global__ void k_blksum() {
    int b = blockIdx.x, t = threadIdx.x, i = b * 128 + t;
    int v = (i < NN) ? d_cnt[i] : 0;
#pragma unroll
    for (int o = 16; o; o >>= 1) v += __shfl_xor_sync(0xffffffffu, v, o);
    __shared__ int ws[4];
    if ((t & 31) == 0) ws[t >> 5] = v;
    __syncthreads();
    if (t == 0) d_blk[b] = ws[0] + ws[1] + ws[2] + ws[3];
}
__global__ void k_blkscan() {   // 160 threads
    int t = threadIdx.x, lane = t & 31, w = t >> 5;
    int v = (t < NB) ? d_blk[t] : 0;
    int x = v;
#pragma unroll
    for (int o = 1; o < 32; o <<= 1) {
        int y = __shfl_up_sync(0xffffffffu, x, o);
        if (lane >= o) x += y;
    }
    __shared__ int ws[5];
    if (lane == 31) ws[w] = x;
    __syncthreads();
    int add = 0;
    for (int q = 0; q < w; q++) add += ws[q];
    if (t < NB) d_blk[t] = x - v + add;
}
__global__ void k_apply() {
    int b = blockIdx.x, t = threadIdx.x, i = b * 128 + t;
    int lane = t & 31, w = t >> 5;
    int v = (i < NN) ? d_cnt[i] : 0;
    int x = v;
#pragma unroll
    for (int o = 1; o < 32; o <<= 1) {
        int y = __shfl_up_sync(0xffffffffu, x, o);
        if (lane >= o) x += y;
    }
    __shared__ int ws[4];
    if (lane == 31) ws[w] = x;
    __syncthreads();
    int add = 0;
    for (int q = 0; q < w; q++) add += ws[q];
    int ex = x - v + add + d_blk[b];
    if (i < NN) { d_off[i] = ex; d_cur[i] = ex; }
    if (i == 0) d_off[NN] = ETOT;
}
__global__ void k_scatter(const int* __restrict__ ei) {
    int e = blockIdx.x * blockDim.x + threadIdx.x;
    if (e >= ETOT) return;
    int d, s;
    if (e < EE) { s = ei[e]; d = ei[EE + e]; }
    else        { s = e - EE; d = e - EE; }
    int pos = atomicAdd(&d_cur[d], 1);
    d_csr[pos] = s;
}

// ---------------- z = h @ W via fp16 mma (ldmatrix) + fused att epilogue ----------------
// bm_base allows row-range half launches for cross-layer pipelining.
__global__ void __launch_bounds__(128) k_gemm_att(int l, int bm_base,
                                                  const float* __restrict__ asrc,
                                                  const float* __restrict__ adst) {
    extern __shared__ __half smh[];
    __half* AH = smh;                 // 64 x SPC
    __half* WH = smh + 64 * SPC;

    int tid = threadIdx.x;
    int bm = bm_base + blockIdx.x * 64, bn = blockIdx.y * 64;
    __half* zbuf = &d_zh[(l & 1) * NN * 512];

    int wid = tid >> 5, lane = tid & 31;
    int g = lane >> 2, tig = lane & 3;
    int wm = (wid & 1) * 32, wn = (wid >> 1) * 32;

    uint32_t AHs = (uint32_t)__cvta_generic_to_shared(AH);
    uint32_t WHs = (uint32_t)__cvta_generic_to_shared(WH);

    int q = lane >> 3, rr = lane & 7;
    int a_row = (q & 1) * 8 + rr;
    int a_col = (q >> 1) * 8;
    int b_ko = ((lane >> 3) & 1) * 8;

    float c[2][4][4] = {};

    for (int kc = 0; kc < 128; kc += 64) {
        if (kc) __syncthreads();
#pragma unroll
        for (int i = 0; i < 4; i++) {
            int u = i * 128 + tid;
            int r = u >> 3, c8 = (u & 7) * 8;
            uint4 vh = make_uint4(0u, 0u, 0u, 0u);
            if (bm + r < NN)
                vh = *(const uint4*)&d_hf[(bm + r) * 128 + kc + c8];
            *(uint4*)&AH[r * SPC + c8] = vh;
            *(uint4*)&WH[r * SPC + c8] = *(const uint4*)&d_wtf[(l * 512 + bn + r) * 128 + kc + c8];
        }
        __syncthreads();

#pragma unroll
        for (int ks = 0; ks < 4; ks++) {
            uint32_t a[2][4];
#pragma unroll
            for (int mt = 0; mt < 2; mt++)
                ldmA(a[mt], AHs + ((wm + mt * 16 + a_row) * SPC + ks * 16 + a_col) * 2);
#pragma unroll
            for (int nt = 0; nt < 4; nt++) {
                uint32_t b0, b1;
                ldmB2(b0, b1, WHs + ((wn + nt * 8 + rr) * SPC + ks * 16 + b_ko) * 2);
#pragma unroll
                for (int mt = 0; mt < 2; mt++)
                    mma_f16(c[mt][nt], a[mt][0], a[mt][1], a[mt][2], a[mt][3], b0, b1);
            }
        }
    }

    // store z as fp16 (layer-parity buffer)
#pragma unroll
    for (int mt = 0; mt < 2; mt++) {
        int r0 = bm + wm + mt * 16 + g;
#pragma unroll
        for (int nt = 0; nt < 4; nt++) {
            int col = bn + wn + nt * 8 + 2 * tig;
            if (r0 < NN)
                *(__half2*)&zbuf[r0 * 512 + col] =
                    __float22half2_rn(make_float2(c[mt][nt][0], c[mt][nt][1]));
            if (r0 + 8 < NN)
                *(__half2*)&zbuf[(r0 + 8) * 512 + col] =
                    __float22half2_rn(make_float2(c[mt][nt][2], c[mt][nt][3]));
        }
    }

    // fused attention-logit epilogue
    int h = bn >> 7;
    int cihbase = (bn & 127) + wn;
    float* esb = &d_es[l * NN * 4];
    float* edb = &d_ed[l * NN * 4];
    float ps[2][2] = {}, pd[2][2] = {};
#pragma unroll
    for (int mt = 0; mt < 2; mt++) {
#pragma unroll
        for (int nt = 0; nt < 4; nt++) {
            int cih = cihbase + nt * 8 + 2 * tig;
            float a0 = asrc[h * 128 + cih], a1 = asrc[h * 128 + cih + 1];
            float d0 = adst[h * 128 + cih], d1 = adst[h * 128 + cih + 1];
            ps[mt][0] += c[mt][nt][0] * a0 + c[mt][nt][1] * a1;
            pd[mt][0] += c[mt][nt][0] * d0 + c[mt][nt][1] * d1;
            ps[mt][1] += c[mt][nt][2] * a0 + c[mt][nt][3] * a1;
            pd[mt][1] += c[mt][nt][2] * d0 + c[mt][nt][3] * d1;
        }
    }
#pragma unroll
    for (int o = 1; o < 4; o <<= 1) {
#pragma unroll
        for (int mt = 0; mt < 2; mt++) {
#pragma unroll
            for (int rh = 0; rh < 2; rh++) {
                ps[mt][rh] += __shfl_xor_sync(0xffffffffu, ps[mt][rh], o);
                pd[mt][rh] += __shfl_xor_sync(0xffffffffu, pd[mt][rh], o);
            }
        }
    }
    if (tig == 0) {
#pragma unroll
        for (int mt = 0; mt < 2; mt++) {
#pragma unroll
            for (int rh = 0; rh < 2; rh++) {
                int r = bm + wm + mt * 16 + g + rh * 8;
                if (r < NN) {
                    atomicAdd(&esb[r * 4 + h], ps[mt][rh]);
                    atomicAdd(&edb[r * 4 + h], pd[mt][rh]);
                }
            }
        }
    }
}

// ---------------- fused softmax-aggregate + head-mean + LN + relu + residual ----
// n_base allows node-range half launches for cross-layer pipelining.
__global__ void k_fused(int l, int n_base,
                        const float* __restrict__ gb,
                        const float* __restrict__ lg,
                        const float* __restrict__ lb) {
    int wid = threadIdx.x >> 5, lane = threadIdx.x & 31;
    int n = n_base + blockIdx.x * 8 + wid;
    if (n >= NN) return;

    const float* esb = &d_es[l * NN * 4];
    const float* edb = &d_ed[l * NN * 4];
    const __half* zbuf = &d_zh[(l & 1) * NN * 512];

    float4 ed4 = *(const float4*)&edb[n * 4];
    float edv[4] = {ed4.x, ed4.y, ed4.z, ed4.w};
    float sden[4] = {0.f, 0.f, 0.f, 0.f};
    float acc[4][4] = {};

#define EDGE_BODY(sidx)                                                         \
    {                                                                           \
        int s_ = (sidx);                                                        \
        float4 es4 = *(const float4*)&esb[s_ * 4];                              \
        const uint2* zr = (const uint2*)&zbuf[s_ * 512];                        \
        uint2 zu0 = zr[lane];                                                   \
        uint2 zu1 = zr[32 + lane];                                              \
        uint2 zu2 = zr[64 + lane];                                              \
        uint2 zu3 = zr[96 + lane];                                              \
        float e0 = es4.x + edv[0], e1 = es4.y + edv[1];                         \
        float e2 = es4.z + edv[2], e3 = es4.w + edv[3];                         \
        e0 = (e0 > 0.f) ? e0 : 0.2f * e0;                                       \
        e1 = (e1 > 0.f) ? e1 : 0.2f * e1;                                       \
        e2 = (e2 > 0.f) ? e2 : 0.2f * e2;                                       \
        e3 = (e3 > 0.f) ? e3 : 0.2f * e3;                                       \
        float p0 = __expf(e0), p1 = __expf(e1);                                 \
        float p2 = __expf(e2), p3 = __expf(e3);                                 \
        sden[0] += p0; sden[1] += p1; sden[2] += p2; sden[3] += p3;             \
        float2 a0 = __half22float2(*(const __half2*)&zu0.x);                    \
        float2 b0 = __half22float2(*(const __half2*)&zu0.y);                    \
        acc[0][0] += p0 * a0.x; acc[0][1] += p0 * a0.y;                         \
        acc[0][2] += p0 * b0.x; acc[0][3] += p0 * b0.y;                         \
        float2 a1 = __half22float2(*(const __half2*)&zu1.x);                    \
        float2 b1 = __half22float2(*(const __half2*)&zu1.y);                    \
        acc[1][0] += p1 * a1.x; acc[1][1] += p1 * a1.y;                         \
        acc[1][2] += p1 * b1.x; acc[1][3] += p1 * b1.y;                         \
        float2 a2 = __half22float2(*(const __half2*)&zu2.x);                    \
        float2 b2 = __half22float2(*(const __half2*)&zu2.y);                    \
        acc[2][0] += p2 * a2.x; acc[2][1] += p2 * a2.y;                         \
        acc[2][2] += p2 * b2.x; acc[2][3] += p2 * b2.y;                         \
        float2 a3 = __half22float2(*(const __half2*)&zu3.x);                    \
        float2 b3 = __half22float2(*(const __half2*)&zu3.y);                    \
        acc[3][0] += p3 * a3.x; acc[3][1] += p3 * a3.y;                         \
        acc[3][2] += p3 * b3.x; acc[3][3] += p3 * b3.y;                         \
    }

    int beg = d_off[n], end = d_off[n + 1];
    int e = beg;
    for (; e + 1 < end; e += 2) {
        int s0 = d_csr[e];
        int s1 = d_csr[e + 1];
        EDGE_BODY(s0);
        EDGE_BODY(s1);
    }
    if (e < end) EDGE_BODY(d_csr[e]);
#undef EDGE_BODY

    float hv[4];
#pragma unroll
    for (int c = 0; c < 4; c++) {
        hv[c] = 0.25f * (acc[0][c] / sden[0] + acc[1][c] / sden[1] +
                         acc[2][c] / sden[2] + acc[3][c] / sden[3]) +
                gb[lane * 4 + c];
    }
    float s1 = hv[0] + hv[1] + hv[2] + hv[3];
    float s2 = hv[0] * hv[0] + hv[1] * hv[1] + hv[2] * hv[2] + hv[3] * hv[3];
#pragma unroll
    for (int o = 16; o > 0; o >>= 1) {
        s1 += __shfl_xor_sync(0xffffffffu, s1, o);
        s2 += __shfl_xor_sync(0xffffffffu, s2, o);
    }
    float mu = s1 * (1.f / 128.f);
    float var = s2 * (1.f / 128.f) - mu * mu;
    float rstd = rsqrtf(var + 1e-5f);

    float4 hold = *(const float4*)&d_h[n * 128 + lane * 4];
    float ho[4] = {hold.x, hold.y, hold.z, hold.w};
    float outv[4];
    __half oh[4];
#pragma unroll
    for (int c = 0; c < 4; c++) {
        int d = lane * 4 + c;
        float v = (hv[c] - mu) * rstd * lg[d] + lb[d];
        outv[c] = fmaxf(v, 0.f) + ho[c];
        oh[c] = __float2half(outv[c]);
    }
    *(float4*)&d_h[n * 128 + lane * 4] = make_float4(outv[0], outv[1], outv[2], outv[3]);
    *(uint2*)&d_hf[n * 128 + lane * 4] = *(uint2*)oh;
}

// ---------------- P/Q for pair MLP layer 1 ----------------
__global__ void k_pq(const int* __restrict__ odd,
                     const float* __restrict__ sW1,
                     const float* __restrict__ sb1) {
    int i = blockIdx.x, c = threadIdx.x;
    __shared__ float hs[128];
    hs[c] = d_h[odd[i] * 128 + c];
    __syncthreads();
    float p = sb1[c], q = 0.f;
#pragma unroll 8
    for (int k = 0; k < 128; k++) {
        float hk = hs[k];
        p += hk * sW1[k * 128 + c];
        q += hk * sW1[(128 + k) * 128 + c];
    }
    d_P[i * 128 + c] = p;
    d_Q[i * 128 + c] = q;
}

// ---------------- pair scoring: bf16x3 mma (ldmatrix), W2 k-chunked smem ----------------
// smem: A hi/lo [64][SP] (full k=128) + W hi/lo [128][SPC] (k=64 chunk) = 71680 B
__global__ void __launch_bounds__(128) k_pair_mma(const float* __restrict__ sb2,
                                                  const float* __restrict__ sW3,
                                                  const float* __restrict__ sb3,
                                                  float* __restrict__ out) {
    int t = blockIdx.x;
    int bx = (int)((129.0f - sqrtf(16641.0f - 8.0f * (float)t)) * 0.5f);
    if (bx > 63) bx = 63;
    while (bx > 0 && 64 * bx - (bx * (bx - 1)) / 2 > t) bx--;
    while (64 * (bx + 1) - ((bx + 1) * bx) / 2 <= t) bx++;
    int by = bx + (t - (64 * bx - (bx * (bx - 1)) / 2));

    extern __shared__ __nv_bfloat16 smb[];
    __nv_bfloat16* AH = smb;                       // 64 x SP
    __nv_bfloat16* AL = smb + 64 * SP;
    __nv_bfloat16* WH = smb + 2 * 64 * SP;         // 128 x SPC (chunk)
    __nv_bfloat16* WL = smb + 2 * 64 * SP + 128 * SPC;

    int tid = threadIdx.x;

    // A build: 8 P + 8 Q register loads, 64 combos (was 128 loads)
    {
        float p8[8], q8[8];
#pragma unroll
        for (int r = 0; r < 8; r++) {
            p8[r] = d_P[(bx * 8 + r) * 128 + tid];
            q8[r] = d_Q[(by * 8 + r) * 128 + tid];
        }
#pragma unroll
        for (int r = 0; r < 8; r++) {
#pragma unroll
            for (int cc = 0; cc < 8; cc++) {
                float v = fmaxf(p8[r] + q8[cc], 0.f);
                __nv_bfloat16 hi, lo; bsplit(v, hi, lo);
                int p = r * 8 + cc;
                AH[p * SP + tid] = hi;
                AL[p * SP + tid] = lo;
            }
        }
    }

    int wid = tid >> 5, lane = tid & 31;
    int g = lane >> 2, tig = lane & 3;
    int wm = (wid & 1) * 32, wn = (wid >> 1) * 64;

    uint32_t AHs = (uint32_t)__cvta_generic_to_shared(AH);
    uint32_t ALs = (uint32_t)__cvta_generic_to_shared(AL);
    uint32_t WHs = (uint32_t)__cvta_generic_to_shared(WH);
    uint32_t WLs = (uint32_t)__cvta_generic_to_shared(WL);

    int q = lane >> 3, rr = lane & 7;
    int a_row = (q & 1) * 8 + rr;
    int a_col = (q >> 1) * 8;
    int b_ko = ((lane >> 3) & 1) * 8;

    float c[2][8][4] = {};

    for (int kc = 0; kc < 128; kc += 64) {
        if (kc) __syncthreads();   // drain prior-chunk W consumers
        // stage W2 chunk [128 n][64 k]
#pragma unroll
        for (int i = 0; i < 8; i++) {
            int u = i * 128 + tid;          // 0..1023
            int n = u >> 3, k8 = (u & 7) * 8;
            *(uint4*)&WH[n * SPC + k8] = *(const uint4*)&d_w2t_hi[n * 128 + kc + k8];
            *(uint4*)&WL[n * SPC + k8] = *(const uint4*)&d_w2t_lo[n * 128 + kc + k8];
        }
        __syncthreads();

#pragma unroll
        for (int ks = 0; ks < 4; ks++) {
            int ksg = kc + ks * 16;
            uint32_t aH[2][4], aL[2][4];
#pragma unroll
            for (int mt = 0; mt < 2; mt++) {
                ldmA(aH[mt], AHs + ((wm + mt * 16 + a_row) * SP + ksg + a_col) * 2);
                ldmA(aL[mt], ALs + ((wm + mt * 16 + a_row) * SP + ksg + a_col) * 2);
            }
#pragma unroll
            for (int nt = 0; nt < 8; nt++) {
                uint32_t bH0, bH1, bL0, bL1;
                ldmB2(bH0, bH1, WHs + ((wn + nt * 8 + rr) * SPC + ks * 16 + b_ko) * 2);
                ldmB2(bL0, bL1, WLs + ((wn + nt * 8 + rr) * SPC + ks * 16 + b_ko) * 2);
#pragma unroll
                for (int mt = 0; mt < 2; mt++) {
                    mma_bf16(c[mt][nt], aH[mt][0], aH[mt][1], aH[mt][2], aH[mt][3], bH0, bH1);
                    mma_bf16(c[mt][nt], aH[mt][0], aH[mt][1], aH[mt][2], aH[mt][3], bL0, bL1);
                    mma_bf16(c[mt][nt], aL[mt][0], aL[mt][1], aL[mt][2], aL[mt][3], bH0, bH1);
                }
            }
        }
    }
    __syncthreads();

    float* red = (float*)smb;
#pragma unroll
    for (int mt = 0; mt < 2; mt++) {
        float p0 = 0.f, p1 = 0.f;
#pragma unroll
        for (int nt = 0; nt < 8; nt++) {
            int c0 = wn + nt * 8 + 2 * tig;
            float w30 = sW3[c0], w31 = sW3[c0 + 1];
            float bb0 = sb2[c0], bb1 = sb2[c0 + 1];
            p0 += fmaxf(c[mt][nt][0] + bb0, 0.f) * w30 + fmaxf(c[mt][nt][1] + bb1, 0.f) * w31;
            p1 += fmaxf(c[mt][nt][2] + bb0, 0.f) * w30 + fmaxf(c[mt][nt][3] + bb1, 0.f) * w31;
        }
#pragma unroll
        for (int o = 1; o < 4; o <<= 1) {
            p0 += __shfl_xor_sync(0xffffffffu, p0, o);
            p1 += __shfl_xor_sync(0xffffffffu, p1, o);
        }
        if (tig == 0) {
            int r = wm + mt * 16 + g;
            red[r * 2 + (wid >> 1)] = p0;
            red[(r + 8) * 2 + (wid >> 1)] = p1;
        }
    }
    __syncthreads();
    if (tid < 64) {
        float s = red[tid * 2] + red[tid * 2 + 1] + sb3[0];
        int i = bx * 8 + (tid >> 3), j = by * 8 + (tid & 7);
        if (i < j) {
            out[i * 512 + j] = s;
            out[j * 512 + i] = s;
        } else if (i == j) {
            out[i * 512 + j] = 0.f;
        }
    }
}

// ---------------- launch ----------------
extern "C" void kernel_launch(void* const* d_in, const int* in_sizes, int n_in,
                              void* d_out, int out_size) {
    const float *x = 0, *node_W = 0, *node_b = 0, *gat_W = 0, *att_src = 0,
                *att_dst = 0, *gat_b = 0, *ln_g = 0, *ln_b = 0, *sW1 = 0,
                *sb1 = 0, *sW2 = 0, *sb2 = 0, *sW3 = 0, *sb3 = 0;
    const int *edge_index = 0, *odd = 0;
    int c1536 = 0, c384 = 0, c128 = 0;
    for (int i = 0; i < n_in; i++) {
        const void* p = d_in[i];
        switch (in_sizes[i]) {
            case 100000: x = (const float*)p; break;
            case 640000: edge_index = (const int*)p; break;
            case 512:    odd = (const int*)p; break;
            case 640:    node_W = (const float*)p; break;
            case 196608: gat_W = (const float*)p; break;
            case 1536:   if (c1536++ == 0) att_src = (const float*)p; else att_dst = (const float*)p; break;
            case 384:    if (c384 == 0) gat_b = (const float*)p;
                         else if (c384 == 1) ln_g = (const float*)p;
                         else ln_b = (const float*)p;
                         c384++; break;
            case 32768:  sW1 = (const float*)p; break;
            case 16384:  sW2 = (const float*)p; break;
            case 128:    if (c128 == 0) node_b = (const float*)p;
                         else if (c128 == 1) sb1 = (const float*)p;
                         else if (c128 == 2) sb2 = (const float*)p;
                         else sW3 = (const float*)p;
                         c128++; break;
            case 1:      sb3 = (const float*)p; break;
            default: break;
        }
    }
    float* outp = (float*)d_out;

    const int GEMM_SMEM = 2 * 64 * SPC * 2;                        // 18432 B
    const int PAIR_SMEM = (2 * 64 * SP + 2 * 128 * SPC) * 2;       // 71680 B
    cudaFuncSetAttribute(k_gemm_att, cudaFuncAttributeMaxDynamicSharedMemorySize, GEMM_SMEM);
    cudaFuncSetAttribute(k_pair_mma, cudaFuncAttributeMaxDynamicSharedMemorySize, PAIR_SMEM);

    cudaStream_t sb;
    cudaStreamCreateWithFlags(&sb, cudaStreamNonBlocking);
    cudaEvent_t ev0, evCSR, eA[2], eB[2], eG[2];
    cudaEventCreateWithFlags(&ev0, cudaEventDisableTiming);
    cudaEventCreateWithFlags(&evCSR, cudaEventDisableTiming);
    for (int i = 0; i < 2; i++) {
        cudaEventCreateWithFlags(&eA[i], cudaEventDisableTiming);
        cudaEventCreateWithFlags(&eB[i], cudaEventDisableTiming);
        cudaEventCreateWithFlags(&eG[i], cudaEventDisableTiming);
    }

    k_prologue<<<PRO_GRID, 128>>>(gat_W, sW2, x, node_W, node_b);
    cudaEventRecord(ev0, 0);

    // side stream: CSR build (overlaps gemm layer-0)
    cudaStreamWaitEvent(sb, ev0, 0);
    k_hist<<<(ETOT + 255) / 256, 256, 0, sb>>>(edge_index);
    k_blksum<<<NB, 128, 0, sb>>>();
    k_blkscan<<<1, 160, 0, sb>>>();
    k_apply<<<NB, 128, 0, sb>>>();
    k_scatter<<<(ETOT + 255) / 256, 256, 0, sb>>>(edge_index);
    cudaEventRecord(evCSR, sb);

    // gemm layer 0 (full) on main, concurrent with CSR
    k_gemm_att<<<dim3(313, 8), 128, GEMM_SMEM>>>(0, 0, att_src, att_dst);
    cudaStreamWaitEvent(0, evCSR, 0);

    // pipelined layers: F(l) halves on main; G(l+1) halves on side
    const int FB0 = NSPLIT / 8;                 // 1256 blocks, nodes [0, 10048)
    const int FB1 = (NN - NSPLIT + 7) / 8;      // 1244 blocks, nodes [10048, NN)
    const int GB0 = NSPLIT / 64;                // 157 row-blocks
    const int GB1 = (NN - NSPLIT + 63) / 64;    // 156 row-blocks

    for (int l = 0; l < NLAYERS; l++) {
        k_fused<<<FB0, 256>>>(l, 0, gat_b + l * 128, ln_g + l * 128, ln_b + l * 128);
        if (l < NLAYERS - 1) cudaEventRecord(eA[l], 0);
        k_fused<<<FB1, 256>>>(l, NSPLIT, gat_b + l * 128, ln_g + l * 128, ln_b + l * 128);
        if (l < NLAYERS - 1) {
            cudaEventRecord(eB[l], 0);
            cudaStreamWaitEvent(sb, eA[l], 0);
            k_gemm_att<<<dim3(GB0, 8), 128, GEMM_SMEM, sb>>>(l + 1, 0,
                att_src + (l + 1) * 512, att_dst + (l + 1) * 512);
            cudaStreamWaitEvent(sb, eB[l], 0);
            k_gemm_att<<<dim3(GB1, 8), 128, GEMM_SMEM, sb>>>(l + 1, NSPLIT,
                att_src + (l + 1) * 512, att_dst + (l + 1) * 512);
            cudaEventRecord(eG[l], sb);
            cudaStreamWaitEvent(0, eG[l], 0);
        }
    }

    k_pq<<<NODD, 128>>>(odd, sW1, sb1);
    k_pair_mma<<<2080, 128, PAIR_SMEM>>>(sb2, sW3, sb3, outp);

    cudaEventDestroy(ev0);
    cudaEventDestroy(evCSR);
    for (int i = 0; i < 2; i++) {
        cudaEventDestroy(eA[i]);
        cudaEventDestroy(eB[i]);
        cudaEventDestroy(eG[i]);
    }
    cudaStreamDestroy(sb);
}

// round 14
// speedup vs baseline: 1.5841x; 1.5841x over previous
#include <cuda_runtime.h>
#include <cuda_bf16.h>
#include <cuda_fp16.h>
#include <cstdint>

#define NN 20000
#define EE 320000
#define ETOT 340000   // EE + NN self loops
#define NODD 512
#define HIDD 128
#define NLAYERS 3
#define SP 136        // padded bf16 smem row stride (pair kernel A)
#define SPC 72        // padded fp16 smem row stride (k=64 chunks)
#define NB 157        // ceil(NN/128)

// ---------------- static scratch ----------------
__device__ float d_h[NN * HIDD];
__device__ __half d_hf[NN * HIDD];          // h in fp16 (gemm A operand)
__device__ __half d_zh[NN * 512];           // z in fp16
__device__ float d_es[NLAYERS * NN * 4];    // per-layer (zeroed once)
__device__ float d_ed[NLAYERS * NN * 4];
__device__ int   d_cnt[NN];
__device__ int   d_cur[NN];
__device__ int   d_off[NN + 1];
__device__ int   d_csr[ETOT];
__device__ int   d_blk[NB + 8];
__device__ float d_P[NODD * HIDD];
__device__ float d_Q[NODD * HIDD];
__device__ __half d_wtf[NLAYERS * 512 * 128];            // gat_W transposed fp16 [l][n][k]
__device__ __nv_bfloat16 d_w2t_hi[128 * 128];            // sW2 transposed (pair: bf16x3)
__device__ __nv_bfloat16 d_w2t_lo[128 * 128];

__device__ __forceinline__ void bsplit(float v, __nv_bfloat16& hi, __nv_bfloat16& lo) {
    hi = __float2bfloat16(v);
    lo = __float2bfloat16(v - __bfloat162float(hi));
}

__device__ __forceinline__ void mma_bf16(float* c, uint32_t a0, uint32_t a1, uint32_t a2,
                                         uint32_t a3, uint32_t b0, uint32_t b1) {
    asm volatile(
        "mma.sync.aligned.m16n8k16.row.col.f32.bf16.bf16.f32 "
        "{%0,%1,%2,%3}, {%4,%5,%6,%7}, {%8,%9}, {%0,%1,%2,%3};\n"
        : "+f"(c[0]), "+f"(c[1]), "+f"(c[2]), "+f"(c[3])
        : "r"(a0), "r"(a1), "r"(a2), "r"(a3), "r"(b0), "r"(b1));
}

__device__ __forceinline__ void mma_f16(float* c, uint32_t a0, uint32_t a1, uint32_t a2,
                                        uint32_t a3, uint32_t b0, uint32_t b1) {
    asm volatile(
        "mma.sync.aligned.m16n8k16.row.col.f32.f16.f16.f32 "
        "{%0,%1,%2,%3}, {%4,%5,%6,%7}, {%8,%9}, {%0,%1,%2,%3};\n"
        : "+f"(c[0]), "+f"(c[1]), "+f"(c[2]), "+f"(c[3])
        : "r"(a0), "r"(a1), "r"(a2), "r"(a3), "r"(b0), "r"(b1));
}

__device__ __forceinline__ void ldmA(uint32_t* a, uint32_t saddr) {
    asm volatile("ldmatrix.sync.aligned.m8n8.x4.shared.b16 {%0,%1,%2,%3}, [%4];"
                 : "=r"(a[0]), "=r"(a[1]), "=r"(a[2]), "=r"(a[3]) : "r"(saddr));
}
__device__ __forceinline__ void ldmB2(uint32_t& b0, uint32_t& b1, uint32_t saddr) {
    asm volatile("ldmatrix.sync.aligned.m8n8.x2.shared.b16 {%0,%1}, [%2];"
                 : "=r"(b0), "=r"(b1) : "r"(saddr));
}

// ---------------- prologue: prep_w + prep_w2 + node_proj + all zeroing ----------------
#define PRO_W   1536
#define PRO_W2  128
#define PRO_NP  20000
#define PRO_Z   1875
#define PRO_GRID (PRO_W + PRO_W2 + PRO_NP + PRO_Z)

__global__ void k_prologue(const float* __restrict__ gw,
                           const float* __restrict__ w2,
                           const float* __restrict__ x,
                           const float* __restrict__ nW,
                           const float* __restrict__ nb) {
    int b = blockIdx.x, t = threadIdx.x;
    if (b < PRO_W) {
        int l = b >> 9, n = b & 511;
        d_wtf[(l * 512 + n) * 128 + t] = __float2half(gw[(l * 128 + t) * 512 + n]);
    } else if (b < PRO_W + PRO_W2) {
        int n = b - PRO_W;
        float v = w2[t * 128 + n];
        __nv_bfloat16 hi, lo; bsplit(v, hi, lo);
        d_w2t_hi[n * 128 + t] = hi;
        d_w2t_lo[n * 128 + t] = lo;
    } else if (b < PRO_W + PRO_W2 + PRO_NP) {
        int n = b - PRO_W - PRO_W2;
        float acc = nb[t];
#pragma unroll
        for (int k = 0; k < 5; k++) acc += x[n * 5 + k] * nW[k * HIDD + t];
        acc = fmaxf(acc, 0.f);
        d_h[n * HIDD + t] = acc;
        d_hf[n * HIDD + t] = __float2half(acc);
    } else {
        int i = (b - PRO_W - PRO_W2 - PRO_NP) * 128 + t;
        if (i < NN) d_cnt[i] = 0;
        if (i < NLAYERS * NN * 4) { d_es[i] = 0.f; d_ed[i] = 0.f; }
    }
}

// ---------------- CSR build ----------------
__global__ void k_hist(const int* __restrict__ ei) {
    int e = blockIdx.x * blockDim.x + threadIdx.x;
    if (e >= ETOT) return;
    int d = (e < EE) ? ei[EE + e] : (e - EE);
    atomicAdd(&d_cnt[d], 1);
}
__global__ void k_blksum() {
    int b = blockIdx.x, t = threadIdx.x, i = b * 128 + t;
    int v = (i < NN) ? d_cnt[i] : 0;
#pragma unroll
    for (int o = 16; o; o >>= 1) v += __shfl_xor_sync(0xffffffffu, v, o);
    __shared__ int ws[4];
    if ((t & 31) == 0) ws[t >> 5] = v;
    __syncthreads();
    if (t == 0) d_blk[b] = ws[0] + ws[1] + ws[2] + ws[3];
}
__global__ void k_blkscan() {   // 160 threads
    int t = threadIdx.x, lane = t & 31, w = t >> 5;
    int v = (t < NB) ? d_blk[t] : 0;
    int x = v;
#pragma unroll
    for (int o = 1; o < 32; o <<= 1) {
        int y = __shfl_up_sync(0xffffffffu, x, o);
        if (lane >= o) x += y;
    }
    __shared__ int ws[5];
    if (lane == 31) ws[w] = x;
    __syncthreads();
    int add = 0;
    for (int q = 0; q < w; q++) add += ws[q];
    if (t < NB) d_blk[t] = x - v + add;
}
__global__ void k_apply() {
    int b = blockIdx.x, t = threadIdx.x, i = b * 128 + t;
    int lane = t & 31, w = t >> 5;
    int v = (i < NN) ? d_cnt[i] : 0;
    int x = v;
#pragma unroll
    for (int o = 1; o < 32; o <<= 1) {
        int y = __shfl_up_sync(0xffffffffu, x, o);
        if (lane >= o) x += y;
    }
    __shared__ int ws[4];
    if (lane == 31) ws[w] = x;
    __syncthreads();
    int add = 0;
    for (int q = 0; q < w; q++) add += ws[q];
    int ex = x - v + add + d_blk[b];
    if (i < NN) { d_off[i] = ex; d_cur[i] = ex; }
    if (i == 0) d_off[NN] = ETOT;
}
__global__ void k_scatter(const int* __restrict__ ei) {
    int e = blockIdx.x * blockDim.x + threadIdx.x;
    if (e >= ETOT) return;
    int d, s;
    if (e < EE) { s = ei[e]; d = ei[EE + e]; }
    else        { s = e - EE; d = e - EE; }
    int pos = atomicAdd(&d_cur[d], 1);
    d_csr[pos] = s;
}

// ---------------- z = h @ W via fp16 mma (ldmatrix) + fused att epilogue ----------------
__global__ void __launch_bounds__(128) k_gemm_att(int l,
                                                  const float* __restrict__ asrc,
                                                  const float* __restrict__ adst) {
    extern __shared__ __half smh[];
    __half* AH = smh;                 // 64 x SPC
    __half* WH = smh + 64 * SPC;

    int tid = threadIdx.x;
    int bm = blockIdx.x * 64, bn = blockIdx.y * 64;

    int wid = tid >> 5, lane = tid & 31;
    int g = lane >> 2, tig = lane & 3;
    int wm = (wid & 1) * 32, wn = (wid >> 1) * 32;

    uint32_t AHs = (uint32_t)__cvta_generic_to_shared(AH);
    uint32_t WHs = (uint32_t)__cvta_generic_to_shared(WH);

    int q = lane >> 3, rr = lane & 7;
    int a_row = (q & 1) * 8 + rr;
    int a_col = (q >> 1) * 8;
    int b_ko = ((lane >> 3) & 1) * 8;

    float c[2][4][4] = {};

    for (int kc = 0; kc < 128; kc += 64) {
        if (kc) __syncthreads();
#pragma unroll
        for (int i = 0; i < 4; i++) {
            int u = i * 128 + tid;
            int r = u >> 3, c8 = (u & 7) * 8;
            uint4 vh = make_uint4(0u, 0u, 0u, 0u);
            if (bm + r < NN)
                vh = *(const uint4*)&d_hf[(bm + r) * 128 + kc + c8];
            *(uint4*)&AH[r * SPC + c8] = vh;
            *(uint4*)&WH[r * SPC + c8] = *(const uint4*)&d_wtf[(l * 512 + bn + r) * 128 + kc + c8];
        }
        __syncthreads();

#pragma unroll
        for (int ks = 0; ks < 4; ks++) {
            uint32_t a[2][4];
#pragma unroll
            for (int mt = 0; mt < 2; mt++)
                ldmA(a[mt], AHs + ((wm + mt * 16 + a_row) * SPC + ks * 16 + a_col) * 2);
#pragma unroll
            for (int nt = 0; nt < 4; nt++) {
                uint32_t b0, b1;
                ldmB2(b0, b1, WHs + ((wn + nt * 8 + rr) * SPC + ks * 16 + b_ko) * 2);
#pragma unroll
                for (int mt = 0; mt < 2; mt++)
                    mma_f16(c[mt][nt], a[mt][0], a[mt][1], a[mt][2], a[mt][3], b0, b1);
            }
        }
    }

    // store z as fp16
#pragma unroll
    for (int mt = 0; mt < 2; mt++) {
        int r0 = bm + wm + mt * 16 + g;
#pragma unroll
        for (int nt = 0; nt < 4; nt++) {
            int col = bn + wn + nt * 8 + 2 * tig;
            if (r0 < NN)
                *(__half2*)&d_zh[r0 * 512 + col] =
                    __float22half2_rn(make_float2(c[mt][nt][0], c[mt][nt][1]));
            if (r0 + 8 < NN)
                *(__half2*)&d_zh[(r0 + 8) * 512 + col] =
                    __float22half2_rn(make_float2(c[mt][nt][2], c[mt][nt][3]));
        }
    }

    // fused attention-logit epilogue
    int h = bn >> 7;
    int cihbase = (bn & 127) + wn;
    float* esb = &d_es[l * NN * 4];
    float* edb = &d_ed[l * NN * 4];
    float ps[2][2] = {}, pd[2][2] = {};
#pragma unroll
    for (int mt = 0; mt < 2; mt++) {
#pragma unroll
        for (int nt = 0; nt < 4; nt++) {
            int cih = cihbase + nt * 8 + 2 * tig;
            float a0 = asrc[h * 128 + cih], a1 = asrc[h * 128 + cih + 1];
            float d0 = adst[h * 128 + cih], d1 = adst[h * 128 + cih + 1];
            ps[mt][0] += c[mt][nt][0] * a0 + c[mt][nt][1] * a1;
            pd[mt][0] += c[mt][nt][0] * d0 + c[mt][nt][1] * d1;
            ps[mt][1] += c[mt][nt][2] * a0 + c[mt][nt][3] * a1;
            pd[mt][1] += c[mt][nt][2] * d0 + c[mt][nt][3] * d1;
        }
    }
#pragma unroll
    for (int o = 1; o < 4; o <<= 1) {
#pragma unroll
        for (int mt = 0; mt < 2; mt++) {
#pragma unroll
            for (int rh = 0; rh < 2; rh++) {
                ps[mt][rh] += __shfl_xor_sync(0xffffffffu, ps[mt][rh], o);
                pd[mt][rh] += __shfl_xor_sync(0xffffffffu, pd[mt][rh], o);
            }
        }
    }
    if (tig == 0) {
#pragma unroll
        for (int mt = 0; mt < 2; mt++) {
#pragma unroll
            for (int rh = 0; rh < 2; rh++) {
                int r = bm + wm + mt * 16 + g + rh * 8;
                if (r < NN) {
                    atomicAdd(&esb[r * 4 + h], ps[mt][rh]);
                    atomicAdd(&edb[r * 4 + h], pd[mt][rh]);
                }
            }
        }
    }
}

// ---------------- fused softmax-aggregate + head-mean + LN + relu + residual ----
__global__ void k_fused(int l,
                        const float* __restrict__ gb,
                        const float* __restrict__ lg,
                        const float* __restrict__ lb) {
    int wid = threadIdx.x >> 5, lane = threadIdx.x & 31;
    int n = blockIdx.x * 8 + wid;
    if (n >= NN) return;

    const float* esb = &d_es[l * NN * 4];
    const float* edb = &d_ed[l * NN * 4];

    float4 ed4 = *(const float4*)&edb[n * 4];
    float edv[4] = {ed4.x, ed4.y, ed4.z, ed4.w};
    float sden[4] = {0.f, 0.f, 0.f, 0.f};
    float acc[4][4] = {};

#define EDGE_BODY(sidx)                                                         \
    {                                                                           \
        int s_ = (sidx);                                                        \
        float4 es4 = *(const float4*)&esb[s_ * 4];                              \
        const uint2* zr = (const uint2*)&d_zh[s_ * 512];                        \
        uint2 zu0 = zr[lane];                                                   \
        uint2 zu1 = zr[32 + lane];                                              \
        uint2 zu2 = zr[64 + lane];                                              \
        uint2 zu3 = zr[96 + lane];                                              \
        float e0 = es4.x + edv[0], e1 = es4.y + edv[1];                         \
        float e2 = es4.z + edv[2], e3 = es4.w + edv[3];                         \
        e0 = (e0 > 0.f) ? e0 : 0.2f * e0;                                       \
        e1 = (e1 > 0.f) ? e1 : 0.2f * e1;                                       \
        e2 = (e2 > 0.f) ? e2 : 0.2f * e2;                                       \
        e3 = (e3 > 0.f) ? e3 : 0.2f * e3;                                       \
        float p0 = __expf(e0), p1 = __expf(e1);                                 \
        float p2 = __expf(e2), p3 = __expf(e3);                                 \
        sden[0] += p0; sden[1] += p1; sden[2] += p2; sden[3] += p3;             \
        float2 a0 = __half22float2(*(const __half2*)&zu0.x);                    \
        float2 b0 = __half22float2(*(const __half2*)&zu0.y);                    \
        acc[0][0] += p0 * a0.x; acc[0][1] += p0 * a0.y;                         \
        acc[0][2] += p0 * b0.x; acc[0][3] += p0 * b0.y;                         \
        float2 a1 = __half22float2(*(const __half2*)&zu1.x);                    \
        float2 b1 = __half22float2(*(const __half2*)&zu1.y);                    \
        acc[1][0] += p1 * a1.x; acc[1][1] += p1 * a1.y;                         \
        acc[1][2] += p1 * b1.x; acc[1][3] += p1 * b1.y;                         \
        float2 a2 = __half22float2(*(const __half2*)&zu2.x);                    \
        float2 b2 = __half22float2(*(const __half2*)&zu2.y);                    \
        acc[2][0] += p2 * a2.x; acc[2][1] += p2 * a2.y;                         \
        acc[2][2] += p2 * b2.x; acc[2][3] += p2 * b2.y;                         \
        float2 a3 = __half22float2(*(const __half2*)&zu3.x);                    \
        float2 b3 = __half22float2(*(const __half2*)&zu3.y);                    \
        acc[3][0] += p3 * a3.x; acc[3][1] += p3 * a3.y;                         \
        acc[3][2] += p3 * b3.x; acc[3][3] += p3 * b3.y;                         \
    }

    int beg = d_off[n], end = d_off[n + 1];
    int e = beg;
    for (; e + 1 < end; e += 2) {
        int s0 = d_csr[e];
        int s1 = d_csr[e + 1];
        EDGE_BODY(s0);
        EDGE_BODY(s1);
    }
    if (e < end) EDGE_BODY(d_csr[e]);
#undef EDGE_BODY

    float hv[4];
#pragma unroll
    for (int c = 0; c < 4; c++) {
        hv[c] = 0.25f * (acc[0][c] / sden[0] + acc[1][c] / sden[1] +
                         acc[2][c] / sden[2] + acc[3][c] / sden[3]) +
                gb[lane * 4 + c];
    }
    float s1 = hv[0] + hv[1] + hv[2] + hv[3];
    float s2 = hv[0] * hv[0] + hv[1] * hv[1] + hv[2] * hv[2] + hv[3] * hv[3];
#pragma unroll
    for (int o = 16; o > 0; o >>= 1) {
        s1 += __shfl_xor_sync(0xffffffffu, s1, o);
        s2 += __shfl_xor_sync(0xffffffffu, s2, o);
    }
    float mu = s1 * (1.f / 128.f);
    float var = s2 * (1.f / 128.f) - mu * mu;
    float rstd = rsqrtf(var + 1e-5f);

    float4 hold = *(const float4*)&d_h[n * 128 + lane * 4];
    float ho[4] = {hold.x, hold.y, hold.z, hold.w};
    float outv[4];
    __half oh[4];
#pragma unroll
    for (int c = 0; c < 4; c++) {
        int d = lane * 4 + c;
        float v = (hv[c] - mu) * rstd * lg[d] + lb[d];
        outv[c] = fmaxf(v, 0.f) + ho[c];
        oh[c] = __float2half(outv[c]);
    }
    *(float4*)&d_h[n * 128 + lane * 4] = make_float4(outv[0], outv[1], outv[2], outv[3]);
    *(uint2*)&d_hf[n * 128 + lane * 4] = *(uint2*)oh;
}

// ---------------- P/Q for pair MLP layer 1 ----------------
__global__ void k_pq(const int* __restrict__ odd,
                     const float* __restrict__ sW1,
                     const float* __restrict__ sb1) {
    int i = blockIdx.x, c = threadIdx.x;
    __shared__ float hs[128];
    hs[c] = d_h[odd[i] * 128 + c];
    __syncthreads();
    float p = sb1[c], q = 0.f;
#pragma unroll 8
    for (int k = 0; k < 128; k++) {
        float hk = hs[k];
        p += hk * sW1[k * 128 + c];
        q += hk * sW1[(128 + k) * 128 + c];
    }
    d_P[i * 128 + c] = p;
    d_Q[i * 128 + c] = q;
}

// ---------------- pair scoring: bf16x3 mma (ldmatrix), reg A-build + W2 k-chunk ----
// smem: A hi/lo [64][SP] + W hi/lo [128][SPC] = 71680 B -> 3 CTAs/SM
__global__ void __launch_bounds__(128) k_pair_mma(const float* __restrict__ sb2,
                                                  const float* __restrict__ sW3,
                                                  const float* __restrict__ sb3,
                                                  float* __restrict__ out) {
    int t = blockIdx.x;
    int bx = (int)((129.0f - sqrtf(16641.0f - 8.0f * (float)t)) * 0.5f);
    if (bx > 63) bx = 63;
    while (bx > 0 && 64 * bx - (bx * (bx - 1)) / 2 > t) bx--;
    while (64 * (bx + 1) - ((bx + 1) * bx) / 2 <= t) bx++;
    int by = bx + (t - (64 * bx - (bx * (bx - 1)) / 2));

    extern __shared__ __nv_bfloat16 smb[];
    __nv_bfloat16* AH = smb;                       // 64 x SP
    __nv_bfloat16* AL = smb + 64 * SP;
    __nv_bfloat16* WH = smb + 2 * 64 * SP;         // 128 x SPC (chunk)
    __nv_bfloat16* WL = smb + 2 * 64 * SP + 128 * SPC;

    int tid = threadIdx.x;

    // A build: 8 P + 8 Q register loads, 64 combos (was 128 global loads)
    {
        float p8[8], q8[8];
#pragma unroll
        for (int r = 0; r < 8; r++) {
            p8[r] = d_P[(bx * 8 + r) * 128 + tid];
            q8[r] = d_Q[(by * 8 + r) * 128 + tid];
        }
#pragma unroll
        for (int r = 0; r < 8; r++) {
#pragma unroll
            for (int cc = 0; cc < 8; cc++) {
                float v = fmaxf(p8[r] + q8[cc], 0.f);
                __nv_bfloat16 hi, lo; bsplit(v, hi, lo);
                int p = r * 8 + cc;
                AH[p * SP + tid] = hi;
                AL[p * SP + tid] = lo;
            }
        }
    }

    int wid = tid >> 5, lane = tid & 31;
    int g = lane >> 2, tig = lane & 3;
    int wm = (wid & 1) * 32, wn = (wid >> 1) * 64;

    uint32_t AHs = (uint32_t)__cvta_generic_to_shared(AH);
    uint32_t ALs = (uint32_t)__cvta_generic_to_shared(AL);
    uint32_t WHs = (uint32_t)__cvta_generic_to_shared(WH);
    uint32_t WLs = (uint32_t)__cvta_generic_to_shared(WL);

    int q = lane >> 3, rr = lane & 7;
    int a_row = (q & 1) * 8 + rr;
    int a_col = (q >> 1) * 8;
    int b_ko = ((lane >> 3) & 1) * 8;

    float c[2][8][4] = {};

    for (int kc = 0; kc < 128; kc += 64) {
        if (kc) __syncthreads();   // drain prior-chunk W consumers
#pragma unroll
        for (int i = 0; i < 8; i++) {
            int u = i * 128 + tid;          // 0..1023
            int n = u >> 3, k8 = (u & 7) * 8;
            *(uint4*)&WH[n * SPC + k8] = *(const uint4*)&d_w2t_hi[n * 128 + kc + k8];
            *(uint4*)&WL[n * SPC + k8] = *(const uint4*)&d_w2t_lo[n * 128 + kc + k8];
        }
        __syncthreads();

#pragma unroll
        for (int ks = 0; ks < 4; ks++) {
            int ksg = kc + ks * 16;
            uint32_t aH[2][4], aL[2][4];
#pragma unroll
            for (int mt = 0; mt < 2; mt++) {
                ldmA(aH[mt], AHs + ((wm + mt * 16 + a_row) * SP + ksg + a_col) * 2);
                ldmA(aL[mt], ALs + ((wm + mt * 16 + a_row) * SP + ksg + a_col) * 2);
            }
#pragma unroll
            for (int nt = 0; nt < 8; nt++) {
                uint32_t bH0, bH1, bL0, bL1;
                ldmB2(bH0, bH1, WHs + ((wn + nt * 8 + rr) * SPC + ks * 16 + b_ko) * 2);
                ldmB2(bL0, bL1, WLs + ((wn + nt * 8 + rr) * SPC + ks * 16 + b_ko) * 2);
#pragma unroll
                for (int mt = 0; mt < 2; mt++) {
                    mma_bf16(c[mt][nt], aH[mt][0], aH[mt][1], aH[mt][2], aH[mt][3], bH0, bH1);
                    mma_bf16(c[mt][nt], aH[mt][0], aH[mt][1], aH[mt][2], aH[mt][3], bL0, bL1);
                    mma_bf16(c[mt][nt], aL[mt][0], aL[mt][1], aL[mt][2], aL[mt][3], bH0, bH1);
                }
            }
        }
    }
    __syncthreads();

    float* red = (float*)smb;
#pragma unroll
    for (int mt = 0; mt < 2; mt++) {
        float p0 = 0.f, p1 = 0.f;
#pragma unroll
        for (int nt = 0; nt < 8; nt++) {
            int c0 = wn + nt * 8 + 2 * tig;
            float w30 = sW3[c0], w31 = sW3[c0 + 1];
            float bb0 = sb2[c0], bb1 = sb2[c0 + 1];
            p0 += fmaxf(c[mt][nt][0] + bb0, 0.f) * w30 + fmaxf(c[mt][nt][1] + bb1, 0.f) * w31;
            p1 += fmaxf(c[mt][nt][2] + bb0, 0.f) * w30 + fmaxf(c[mt][nt][3] + bb1, 0.f) * w31;
        }
#pragma unroll
        for (int o = 1; o < 4; o <<= 1) {
            p0 += __shfl_xor_sync(0xffffffffu, p0, o);
            p1 += __shfl_xor_sync(0xffffffffu, p1, o);
        }
        if (tig == 0) {
            int r = wm + mt * 16 + g;
            red[r * 2 + (wid >> 1)] = p0;
            red[(r + 8) * 2 + (wid >> 1)] = p1;
        }
    }
    __syncthreads();
    if (tid < 64) {
        float s = red[tid * 2] + red[tid * 2 + 1] + sb3[0];
        int i = bx * 8 + (tid >> 3), j = by * 8 + (tid & 7);
        if (i < j) {
            out[i * 512 + j] = s;
            out[j * 512 + i] = s;
        } else if (i == j) {
            out[i * 512 + j] = 0.f;
        }
    }
}

// ---------------- launch (R12 structure: simple layer loop + CSR overlap) ----------------
extern "C" void kernel_launch(void* const* d_in, const int* in_sizes, int n_in,
                              void* d_out, int out_size) {
    const float *x = 0, *node_W = 0, *node_b = 0, *gat_W = 0, *att_src = 0,
                *att_dst = 0, *gat_b = 0, *ln_g = 0, *ln_b = 0, *sW1 = 0,
                *sb1 = 0, *sW2 = 0, *sb2 = 0, *sW3 = 0, *sb3 = 0;
    const int *edge_index = 0, *odd = 0;
    int c1536 = 0, c384 = 0, c128 = 0;
    for (int i = 0; i < n_in; i++) {
        const void* p = d_in[i];
        switch (in_sizes[i]) {
            case 100000: x = (const float*)p; break;
            case 640000: edge_index = (const int*)p; break;
            case 512:    odd = (const int*)p; break;
            case 640:    node_W = (const float*)p; break;
            case 196608: gat_W = (const float*)p; break;
            case 1536:   if (c1536++ == 0) att_src = (const float*)p; else att_dst = (const float*)p; break;
            case 384:    if (c384 == 0) gat_b = (const float*)p;
                         else if (c384 == 1) ln_g = (const float*)p;
                         else ln_b = (const float*)p;
                         c384++; break;
            case 32768:  sW1 = (const float*)p; break;
            case 16384:  sW2 = (const float*)p; break;
            case 128:    if (c128 == 0) node_b = (const float*)p;
                         else if (c128 == 1) sb1 = (const float*)p;
                         else if (c128 == 2) sb2 = (const float*)p;
                         else sW3 = (const float*)p;
                         c128++; break;
            case 1:      sb3 = (const float*)p; break;
            default: break;
        }
    }
    float* outp = (float*)d_out;

    const int GEMM_SMEM = 2 * 64 * SPC * 2;                        // 18432 B
    const int PAIR_SMEM = (2 * 64 * SP + 2 * 128 * SPC) * 2;       // 71680 B
    cudaFuncSetAttribute(k_gemm_att, cudaFuncAttributeMaxDynamicSharedMemorySize, GEMM_SMEM);
    cudaFuncSetAttribute(k_pair_mma, cudaFuncAttributeMaxDynamicSharedMemorySize, PAIR_SMEM);

    // fork-join: CSR chain on side stream, overlapped with gemm layer-0
    cudaStream_t sb;
    cudaStreamCreateWithFlags(&sb, cudaStreamNonBlocking);
    cudaEvent_t ev0, ev1;
    cudaEventCreateWithFlags(&ev0, cudaEventDisableTiming);
    cudaEventCreateWithFlags(&ev1, cudaEventDisableTiming);

    k_prologue<<<PRO_GRID, 128>>>(gat_W, sW2, x, node_W, node_b);
    cudaEventRecord(ev0, 0);

    cudaStreamWaitEvent(sb, ev0, 0);
    k_hist<<<(ETOT + 255) / 256, 256, 0, sb>>>(edge_index);
    k_blksum<<<NB, 128, 0, sb>>>();
    k_blkscan<<<1, 160, 0, sb>>>();
    k_apply<<<NB, 128, 0, sb>>>();
    k_scatter<<<(ETOT + 255) / 256, 256, 0, sb>>>(edge_index);
    cudaEventRecord(ev1, sb);

    k_gemm_att<<<dim3(313, 8), 128, GEMM_SMEM>>>(0, att_src, att_dst);
    cudaStreamWaitEvent(0, ev1, 0);
    k_fused<<<(NN + 7) / 8, 256>>>(0, gat_b, ln_g, ln_b);

    for (int l = 1; l < NLAYERS; l++) {
        k_gemm_att<<<dim3(313, 8), 128, GEMM_SMEM>>>(l, att_src + l * 512, att_dst + l * 512);
        k_fused<<<(NN + 7) / 8, 256>>>(l, gat_b + l * 128, ln_g + l * 128, ln_b + l * 128);
    }

    k_pq<<<NODD, 128>>>(odd, sW1, sb1);
    k_pair_mma<<<2080, 128, PAIR_SMEM>>>(sb2, sW3, sb3, outp);

    cudaEventDestroy(ev0);
    cudaEventDestroy(ev1);
    cudaStreamDestroy(sb);
}

// round 15
// speedup vs baseline: 1.6471x; 1.0398x over previous
#include <cuda_runtime.h>
#include <cuda_bf16.h>
#include <cuda_fp16.h>
#include <cstdint>

#define NN 20000
#define EE 320000
#define ETOT 340000   // EE + NN self loops
#define NODD 512
#define HIDD 128
#define NLAYERS 3
#define SP 136        // (unused legacy)
#define SPC 72        // padded 16-bit smem row stride (k=64 chunks)
#define NB 157        // ceil(NN/128)

// ---------------- static scratch ----------------
__device__ float d_h[NN * HIDD];
__device__ __half d_hf[NN * HIDD];          // h in fp16 (gemm A operand)
__device__ __half d_zh[NN * 512];           // z in fp16
__device__ float d_es[NLAYERS * NN * 4];    // per-layer (zeroed once)
__device__ float d_ed[NLAYERS * NN * 4];
__device__ int   d_cnt[NN];
__device__ int   d_cur[NN];
__device__ int   d_off[NN + 1];
__device__ int   d_csr[ETOT];
__device__ int   d_blk[NB + 8];
__device__ float d_P[NODD * HIDD];
__device__ float d_Q[NODD * HIDD];
__device__ __half d_wtf[NLAYERS * 512 * 128];            // gat_W transposed fp16 [l][n][k]
__device__ __nv_bfloat16 d_w2t_hi[128 * 128];            // sW2 transposed (pair: bf16x3)
__device__ __nv_bfloat16 d_w2t_lo[128 * 128];

__device__ __forceinline__ void bsplit(float v, __nv_bfloat16& hi, __nv_bfloat16& lo) {
    hi = __float2bfloat16(v);
    lo = __float2bfloat16(v - __bfloat162float(hi));
}

__device__ __forceinline__ void mma_bf16(float* c, uint32_t a0, uint32_t a1, uint32_t a2,
                                         uint32_t a3, uint32_t b0, uint32_t b1) {
    asm volatile(
        "mma.sync.aligned.m16n8k16.row.col.f32.bf16.bf16.f32 "
        "{%0,%1,%2,%3}, {%4,%5,%6,%7}, {%8,%9}, {%0,%1,%2,%3};\n"
        : "+f"(c[0]), "+f"(c[1]), "+f"(c[2]), "+f"(c[3])
        : "r"(a0), "r"(a1), "r"(a2), "r"(a3), "r"(b0), "r"(b1));
}

__device__ __forceinline__ void mma_f16(float* c, uint32_t a0, uint32_t a1, uint32_t a2,
                                        uint32_t a3, uint32_t b0, uint32_t b1) {
    asm volatile(
        "mma.sync.aligned.m16n8k16.row.col.f32.f16.f16.f32 "
        "{%0,%1,%2,%3}, {%4,%5,%6,%7}, {%8,%9}, {%0,%1,%2,%3};\n"
        : "+f"(c[0]), "+f"(c[1]), "+f"(c[2]), "+f"(c[3])
        : "r"(a0), "r"(a1), "r"(a2), "r"(a3), "r"(b0), "r"(b1));
}

__device__ __forceinline__ void ldmA(uint32_t* a, uint32_t saddr) {
    asm volatile("ldmatrix.sync.aligned.m8n8.x4.shared.b16 {%0,%1,%2,%3}, [%4];"
                 : "=r"(a[0]), "=r"(a[1]), "=r"(a[2]), "=r"(a[3]) : "r"(saddr));
}
__device__ __forceinline__ void ldmB2(uint32_t& b0, uint32_t& b1, uint32_t saddr) {
    asm volatile("ldmatrix.sync.aligned.m8n8.x2.shared.b16 {%0,%1}, [%2];"
                 : "=r"(b0), "=r"(b1) : "r"(saddr));
}

// ---------------- prologue: prep_w + prep_w2 + node_proj + all zeroing ----------------
#define PRO_W   1536
#define PRO_W2  128
#define PRO_NP  20000
#define PRO_Z   1875
#define PRO_GRID (PRO_W + PRO_W2 + PRO_NP + PRO_Z)

__global__ void k_prologue(const float* __restrict__ gw,
                           const float* __restrict__ w2,
                           const float* __restrict__ x,
                           const float* __restrict__ nW,
                           const float* __restrict__ nb) {
    int b = blockIdx.x, t = threadIdx.x;
    if (b < PRO_W) {
        int l = b >> 9, n = b & 511;
        d_wtf[(l * 512 + n) * 128 + t] = __float2half(gw[(l * 128 + t) * 512 + n]);
    } else if (b < PRO_W + PRO_W2) {
        int n = b - PRO_W;
        float v = w2[t * 128 + n];
        __nv_bfloat16 hi, lo; bsplit(v, hi, lo);
        d_w2t_hi[n * 128 + t] = hi;
        d_w2t_lo[n * 128 + t] = lo;
    } else if (b < PRO_W + PRO_W2 + PRO_NP) {
        int n = b - PRO_W - PRO_W2;
        float acc = nb[t];
#pragma unroll
        for (int k = 0; k < 5; k++) acc += x[n * 5 + k] * nW[k * HIDD + t];
        acc = fmaxf(acc, 0.f);
        d_h[n * HIDD + t] = acc;
        d_hf[n * HIDD + t] = __float2half(acc);
    } else {
        int i = (b - PRO_W - PRO_W2 - PRO_NP) * 128 + t;
        if (i < NN) d_cnt[i] = 0;
        if (i < NLAYERS * NN * 4) { d_es[i] = 0.f; d_ed[i] = 0.f; }
    }
}

// ---------------- CSR build ----------------
__global__ void k_hist(const int* __restrict__ ei) {
    int e = blockIdx.x * blockDim.x + threadIdx.x;
    if (e >= ETOT) return;
    int d = (e < EE) ? ei[EE + e] : (e - EE);
    atomicAdd(&d_cnt[d], 1);
}
__global__ void k_blksum() {
    int b = blockIdx.x, t = threadIdx.x, i = b * 128 + t;
    int v = (i < NN) ? d_cnt[i] : 0;
#pragma unroll
    for (int o = 16; o; o >>= 1) v += __shfl_xor_sync(0xffffffffu, v, o);
    __shared__ int ws[4];
    if ((t & 31) == 0) ws[t >> 5] = v;
    __syncthreads();
    if (t == 0) d_blk[b] = ws[0] + ws[1] + ws[2] + ws[3];
}
__global__ void k_blkscan() {   // 160 threads
    int t = threadIdx.x, lane = t & 31, w = t >> 5;
    int v = (t < NB) ? d_blk[t] : 0;
    int x = v;
#pragma unroll
    for (int o = 1; o < 32; o <<= 1) {
        int y = __shfl_up_sync(0xffffffffu, x, o);
        if (lane >= o) x += y;
    }
    __shared__ int ws[5];
    if (lane == 31) ws[w] = x;
    __syncthreads();
    int add = 0;
    for (int q = 0; q < w; q++) add += ws[q];
    if (t < NB) d_blk[t] = x - v + add;
}
__global__ void k_apply() {
    int b = blockIdx.x, t = threadIdx.x, i = b * 128 + t;
    int lane = t & 31, w = t >> 5;
    int v = (i < NN) ? d_cnt[i] : 0;
    int x = v;
#pragma unroll
    for (int o = 1; o < 32; o <<= 1) {
        int y = __shfl_up_sync(0xffffffffu, x, o);
        if (lane >= o) x += y;
    }
    __shared__ int ws[4];
    if (lane == 31) ws[w] = x;
    __syncthreads();
    int add = 0;
    for (int q = 0; q < w; q++) add += ws[q];
    int ex = x - v + add + d_blk[b];
    if (i < NN) { d_off[i] = ex; d_cur[i] = ex; }
    if (i == 0) d_off[NN] = ETOT;
}
__global__ void k_scatter(const int* __restrict__ ei) {
    int e = blockIdx.x * blockDim.x + threadIdx.x;
    if (e >= ETOT) return;
    int d, s;
    if (e < EE) { s = ei[e]; d = ei[EE + e]; }
    else        { s = e - EE; d = e - EE; }
    int pos = atomicAdd(&d_cur[d], 1);
    d_csr[pos] = s;
}

// ---------------- z = h @ W via fp16 mma (ldmatrix), BN=128 tile, one head/block ----
__global__ void __launch_bounds__(128) k_gemm_att(int l,
                                                  const float* __restrict__ asrc,
                                                  const float* __restrict__ adst) {
    extern __shared__ __half smh[];
    __half* AH = smh;                 // 64 x SPC (chunk)
    __half* WH = smh + 64 * SPC;      // 128 x SPC (chunk)

    int tid = threadIdx.x;
    int bm = blockIdx.x * 64;
    int h = blockIdx.y;               // bn = h * 128; one head per block
    int bn = h << 7;

    int wid = tid >> 5, lane = tid & 31;
    int g = lane >> 2, tig = lane & 3;
    int wm = (wid & 1) * 32, wn = (wid >> 1) * 64;

    uint32_t AHs = (uint32_t)__cvta_generic_to_shared(AH);
    uint32_t WHs = (uint32_t)__cvta_generic_to_shared(WH);

    int q = lane >> 3, rr = lane & 7;
    int a_row = (q & 1) * 8 + rr;
    int a_col = (q >> 1) * 8;
    int b_ko = ((lane >> 3) & 1) * 8;

    float c[2][8][4] = {};

    for (int kc = 0; kc < 128; kc += 64) {
        if (kc) __syncthreads();
        // stage A chunk [64 m][64 k]
#pragma unroll
        for (int i = 0; i < 4; i++) {
            int u = i * 128 + tid;
            int r = u >> 3, c8 = (u & 7) * 8;
            uint4 vh = make_uint4(0u, 0u, 0u, 0u);
            if (bm + r < NN)
                vh = *(const uint4*)&d_hf[(bm + r) * 128 + kc + c8];
            *(uint4*)&AH[r * SPC + c8] = vh;
        }
        // stage W chunk [128 n][64 k]
#pragma unroll
        for (int i = 0; i < 8; i++) {
            int u = i * 128 + tid;
            int n = u >> 3, k8 = (u & 7) * 8;
            *(uint4*)&WH[n * SPC + k8] = *(const uint4*)&d_wtf[(l * 512 + bn + n) * 128 + kc + k8];
        }
        __syncthreads();

#pragma unroll
        for (int ks = 0; ks < 4; ks++) {
            uint32_t a[2][4];
#pragma unroll
            for (int mt = 0; mt < 2; mt++)
                ldmA(a[mt], AHs + ((wm + mt * 16 + a_row) * SPC + ks * 16 + a_col) * 2);
#pragma unroll
            for (int nt = 0; nt < 8; nt++) {
                uint32_t b0, b1;
                ldmB2(b0, b1, WHs + ((wn + nt * 8 + rr) * SPC + ks * 16 + b_ko) * 2);
#pragma unroll
                for (int mt = 0; mt < 2; mt++)
                    mma_f16(c[mt][nt], a[mt][0], a[mt][1], a[mt][2], a[mt][3], b0, b1);
            }
        }
    }

    // store z as fp16
#pragma unroll
    for (int mt = 0; mt < 2; mt++) {
        int r0 = bm + wm + mt * 16 + g;
#pragma unroll
        for (int nt = 0; nt < 8; nt++) {
            int col = bn + wn + nt * 8 + 2 * tig;
            if (r0 < NN)
                *(__half2*)&d_zh[r0 * 512 + col] =
                    __float22half2_rn(make_float2(c[mt][nt][0], c[mt][nt][1]));
            if (r0 + 8 < NN)
                *(__half2*)&d_zh[(r0 + 8) * 512 + col] =
                    __float22half2_rn(make_float2(c[mt][nt][2], c[mt][nt][3]));
        }
    }

    // fused attention-logit epilogue: exactly one head per block
    float* esb = &d_es[l * NN * 4];
    float* edb = &d_ed[l * NN * 4];
    float ps[2][2] = {}, pd[2][2] = {};
#pragma unroll
    for (int mt = 0; mt < 2; mt++) {
#pragma unroll
        for (int nt = 0; nt < 8; nt++) {
            int cih = wn + nt * 8 + 2 * tig;
            float a0 = asrc[h * 128 + cih], a1 = asrc[h * 128 + cih + 1];
            float d0 = adst[h * 128 + cih], d1 = adst[h * 128 + cih + 1];
            ps[mt][0] += c[mt][nt][0] * a0 + c[mt][nt][1] * a1;
            pd[mt][0] += c[mt][nt][0] * d0 + c[mt][nt][1] * d1;
            ps[mt][1] += c[mt][nt][2] * a0 + c[mt][nt][3] * a1;
            pd[mt][1] += c[mt][nt][2] * d0 + c[mt][nt][3] * d1;
        }
    }
#pragma unroll
    for (int o = 1; o < 4; o <<= 1) {
#pragma unroll
        for (int mt = 0; mt < 2; mt++) {
#pragma unroll
            for (int rh = 0; rh < 2; rh++) {
                ps[mt][rh] += __shfl_xor_sync(0xffffffffu, ps[mt][rh], o);
                pd[mt][rh] += __shfl_xor_sync(0xffffffffu, pd[mt][rh], o);
            }
        }
    }
    if (tig == 0) {
#pragma unroll
        for (int mt = 0; mt < 2; mt++) {
#pragma unroll
            for (int rh = 0; rh < 2; rh++) {
                int r = bm + wm + mt * 16 + g + rh * 8;
                if (r < NN) {
                    // halves (wid>>1 = 0,1) both cover full head cols 0..127 of
                    // distinct col ranges; atomics combine the two col-halves
                    atomicAdd(&esb[r * 4 + h], ps[mt][rh]);
                    atomicAdd(&edb[r * 4 + h], pd[mt][rh]);
                }
            }
        }
    }
}

// ---------------- fused softmax-aggregate + head-mean + LN + relu + residual ----
__global__ void k_fused(int l,
                        const float* __restrict__ gb,
                        const float* __restrict__ lg,
                        const float* __restrict__ lb) {
    int wid = threadIdx.x >> 5, lane = threadIdx.x & 31;
    int n = blockIdx.x * 8 + wid;
    if (n >= NN) return;

    const float* esb = &d_es[l * NN * 4];
    const float* edb = &d_ed[l * NN * 4];

    float4 ed4 = *(const float4*)&edb[n * 4];
    float edv[4] = {ed4.x, ed4.y, ed4.z, ed4.w};
    float sden[4] = {0.f, 0.f, 0.f, 0.f};
    float acc[4][4] = {};

#define EDGE_BODY(sidx)                                                         \
    {                                                                           \
        int s_ = (sidx);                                                        \
        float4 es4 = *(const float4*)&esb[s_ * 4];                              \
        const uint2* zr = (const uint2*)&d_zh[s_ * 512];                        \
        uint2 zu0 = zr[lane];                                                   \
        uint2 zu1 = zr[32 + lane];                                              \
        uint2 zu2 = zr[64 + lane];                                              \
        uint2 zu3 = zr[96 + lane];                                              \
        float e0 = es4.x + edv[0], e1 = es4.y + edv[1];                         \
        float e2 = es4.z + edv[2], e3 = es4.w + edv[3];                         \
        e0 = (e0 > 0.f) ? e0 : 0.2f * e0;                                       \
        e1 = (e1 > 0.f) ? e1 : 0.2f * e1;                                       \
        e2 = (e2 > 0.f) ? e2 : 0.2f * e2;                                       \
        e3 = (e3 > 0.f) ? e3 : 0.2f * e3;                                       \
        float p0 = __expf(e0), p1 = __expf(e1);                                 \
        float p2 = __expf(e2), p3 = __expf(e3);                                 \
        sden[0] += p0; sden[1] += p1; sden[2] += p2; sden[3] += p3;             \
        float2 a0 = __half22float2(*(const __half2*)&zu0.x);                    \
        float2 b0 = __half22float2(*(const __half2*)&zu0.y);                    \
        acc[0][0] += p0 * a0.x; acc[0][1] += p0 * a0.y;                         \
        acc[0][2] += p0 * b0.x; acc[0][3] += p0 * b0.y;                         \
        float2 a1 = __half22float2(*(const __half2*)&zu1.x);                    \
        float2 b1 = __half22float2(*(const __half2*)&zu1.y);                    \
        acc[1][0] += p1 * a1.x; acc[1][1] += p1 * a1.y;                         \
        acc[1][2] += p1 * b1.x; acc[1][3] += p1 * b1.y;                         \
        float2 a2 = __half22float2(*(const __half2*)&zu2.x);                    \
        float2 b2 = __half22float2(*(const __half2*)&zu2.y);                    \
        acc[2][0] += p2 * a2.x; acc[2][1] += p2 * a2.y;                         \
        acc[2][2] += p2 * b2.x; acc[2][3] += p2 * b2.y;                         \
        float2 a3 = __half22float2(*(const __half2*)&zu3.x);                    \
        float2 b3 = __half22float2(*(const __half2*)&zu3.y);                    \
        acc[3][0] += p3 * a3.x; acc[3][1] += p3 * a3.y;                         \
        acc[3][2] += p3 * b3.x; acc[3][3] += p3 * b3.y;                         \
    }

    int beg = d_off[n], end = d_off[n + 1];
    int e = beg;
    for (; e + 1 < end; e += 2) {
        int s0 = d_csr[e];
        int s1 = d_csr[e + 1];
        EDGE_BODY(s0);
        EDGE_BODY(s1);
    }
    if (e < end) EDGE_BODY(d_csr[e]);
#undef EDGE_BODY

    float hv[4];
#pragma unroll
    for (int c = 0; c < 4; c++) {
        hv[c] = 0.25f * (acc[0][c] / sden[0] + acc[1][c] / sden[1] +
                         acc[2][c] / sden[2] + acc[3][c] / sden[3]) +
                gb[lane * 4 + c];
    }
    float s1 = hv[0] + hv[1] + hv[2] + hv[3];
    float s2 = hv[0] * hv[0] + hv[1] * hv[1] + hv[2] * hv[2] + hv[3] * hv[3];
#pragma unroll
    for (int o = 16; o > 0; o >>= 1) {
        s1 += __shfl_xor_sync(0xffffffffu, s1, o);
        s2 += __shfl_xor_sync(0xffffffffu, s2, o);
    }
    float mu = s1 * (1.f / 128.f);
    float var = s2 * (1.f / 128.f) - mu * mu;
    float rstd = rsqrtf(var + 1e-5f);

    float4 hold = *(const float4*)&d_h[n * 128 + lane * 4];
    float ho[4] = {hold.x, hold.y, hold.z, hold.w};
    float outv[4];
    __half oh[4];
#pragma unroll
    for (int c = 0; c < 4; c++) {
        int d = lane * 4 + c;
        float v = (hv[c] - mu) * rstd * lg[d] + lb[d];
        outv[c] = fmaxf(v, 0.f) + ho[c];
        oh[c] = __float2half(outv[c]);
    }
    *(float4*)&d_h[n * 128 + lane * 4] = make_float4(outv[0], outv[1], outv[2], outv[3]);
    *(uint2*)&d_hf[n * 128 + lane * 4] = *(uint2*)oh;
}

// ---------------- P/Q for pair MLP layer 1 ----------------
__global__ void k_pq(const int* __restrict__ odd,
                     const float* __restrict__ sW1,
                     const float* __restrict__ sb1) {
    int i = blockIdx.x, c = threadIdx.x;
    __shared__ float hs[128];
    hs[c] = d_h[odd[i] * 128 + c];
    __syncthreads();
    float p = sb1[c], q = 0.f;
#pragma unroll 8
    for (int k = 0; k < 128; k++) {
        float hk = hs[k];
        p += hk * sW1[k * 128 + c];
        q += hk * sW1[(128 + k) * 128 + c];
    }
    d_P[i * 128 + c] = p;
    d_Q[i * 128 + c] = q;
}

// ---------------- pair scoring: bf16x3 mma (ldmatrix), A+W both k-chunked ----------
// smem: A hi/lo [64][SPC] + W hi/lo [128][SPC] = 55296 B -> 4 CTAs/SM
__global__ void __launch_bounds__(128) k_pair_mma(const float* __restrict__ sb2,
                                                  const float* __restrict__ sW3,
                                                  const float* __restrict__ sb3,
                                                  float* __restrict__ out) {
    int t = blockIdx.x;
    int bx = (int)((129.0f - sqrtf(16641.0f - 8.0f * (float)t)) * 0.5f);
    if (bx > 63) bx = 63;
    while (bx > 0 && 64 * bx - (bx * (bx - 1)) / 2 > t) bx--;
    while (64 * (bx + 1) - ((bx + 1) * bx) / 2 <= t) bx++;
    int by = bx + (t - (64 * bx - (bx * (bx - 1)) / 2));

    extern __shared__ __nv_bfloat16 smb[];
    __nv_bfloat16* AH = smb;                       // 64 x SPC (chunk)
    __nv_bfloat16* AL = smb + 64 * SPC;
    __nv_bfloat16* WH = smb + 2 * 64 * SPC;        // 128 x SPC (chunk)
    __nv_bfloat16* WL = smb + 2 * 64 * SPC + 128 * SPC;

    int tid = threadIdx.x;
    int wid = tid >> 5, lane = tid & 31;
    int g = lane >> 2, tig = lane & 3;
    int wm = (wid & 1) * 32, wn = (wid >> 1) * 64;

    uint32_t AHs = (uint32_t)__cvta_generic_to_shared(AH);
    uint32_t ALs = (uint32_t)__cvta_generic_to_shared(AL);
    uint32_t WHs = (uint32_t)__cvta_generic_to_shared(WH);
    uint32_t WLs = (uint32_t)__cvta_generic_to_shared(WL);

    int q = lane >> 3, rr = lane & 7;
    int a_row = (q & 1) * 8 + rr;
    int a_col = (q >> 1) * 8;
    int b_ko = ((lane >> 3) & 1) * 8;

    // A-build thread mapping: kk = k within chunk, half selects pair rows
    int kk = tid & 63;
    int half = tid >> 6;   // 0: pairs 0..31 (r 0..3), 1: pairs 32..63 (r 4..7)

    float c[2][8][4] = {};

    for (int kc = 0; kc < 128; kc += 64) {
        if (kc) __syncthreads();   // drain prior-chunk consumers
        // build A chunk from P/Q (registers)
        {
            float p4[4], q8[8];
#pragma unroll
            for (int r = 0; r < 4; r++)
                p4[r] = d_P[(bx * 8 + half * 4 + r) * 128 + kc + kk];
#pragma unroll
            for (int cc = 0; cc < 8; cc++)
                q8[cc] = d_Q[(by * 8 + cc) * 128 + kc + kk];
#pragma unroll
            for (int r = 0; r < 4; r++) {
#pragma unroll
                for (int cc = 0; cc < 8; cc++) {
                    float v = fmaxf(p4[r] + q8[cc], 0.f);
                    __nv_bfloat16 hi, lo; bsplit(v, hi, lo);
                    int p = (half * 4 + r) * 8 + cc;
                    AH[p * SPC + kk] = hi;
                    AL[p * SPC + kk] = lo;
                }
            }
        }
        // stage W2 chunk [128 n][64 k]
#pragma unroll
        for (int i = 0; i < 8; i++) {
            int u = i * 128 + tid;
            int n = u >> 3, k8 = (u & 7) * 8;
            *(uint4*)&WH[n * SPC + k8] = *(const uint4*)&d_w2t_hi[n * 128 + kc + k8];
            *(uint4*)&WL[n * SPC + k8] = *(const uint4*)&d_w2t_lo[n * 128 + kc + k8];
        }
        __syncthreads();

#pragma unroll
        for (int ks = 0; ks < 4; ks++) {
            uint32_t aH[2][4], aL[2][4];
#pragma unroll
            for (int mt = 0; mt < 2; mt++) {
                ldmA(aH[mt], AHs + ((wm + mt * 16 + a_row) * SPC + ks * 16 + a_col) * 2);
                ldmA(aL[mt], ALs + ((wm + mt * 16 + a_row) * SPC + ks * 16 + a_col) * 2);
            }
#pragma unroll
            for (int nt = 0; nt < 8; nt++) {
                uint32_t bH0, bH1, bL0, bL1;
                ldmB2(bH0, bH1, WHs + ((wn + nt * 8 + rr) * SPC + ks * 16 + b_ko) * 2);
                ldmB2(bL0, bL1, WLs + ((wn + nt * 8 + rr) * SPC + ks * 16 + b_ko) * 2);
#pragma unroll
                for (int mt = 0; mt < 2; mt++) {
                    mma_bf16(c[mt][nt], aH[mt][0], aH[mt][1], aH[mt][2], aH[mt][3], bH0, bH1);
                    mma_bf16(c[mt][nt], aH[mt][0], aH[mt][1], aH[mt][2], aH[mt][3], bL0, bL1);
                    mma_bf16(c[mt][nt], aL[mt][0], aL[mt][1], aL[mt][2], aL[mt][3], bH0, bH1);
                }
            }
        }
    }
    __syncthreads();

    float* red = (float*)smb;
#pragma unroll
    for (int mt = 0; mt < 2; mt++) {
        float p0 = 0.f, p1 = 0.f;
#pragma unroll
        for (int nt = 0; nt < 8; nt++) {
            int c0 = wn + nt * 8 + 2 * tig;
            float w30 = sW3[c0], w31 = sW3[c0 + 1];
            float bb0 = sb2[c0], bb1 = sb2[c0 + 1];
            p0 += fmaxf(c[mt][nt][0] + bb0, 0.f) * w30 + fmaxf(c[mt][nt][1] + bb1, 0.f) * w31;
            p1 += fmaxf(c[mt][nt][2] + bb0, 0.f) * w30 + fmaxf(c[mt][nt][3] + bb1, 0.f) * w31;
        }
#pragma unroll
        for (int o = 1; o < 4; o <<= 1) {
            p0 += __shfl_xor_sync(0xffffffffu, p0, o);
            p1 += __shfl_xor_sync(0xffffffffu, p1, o);
        }
        if (tig == 0) {
            int r = wm + mt * 16 + g;
            red[r * 2 + (wid >> 1)] = p0;
            red[(r + 8) * 2 + (wid >> 1)] = p1;
        }
    }
    __syncthreads();
    if (tid < 64) {
        float s = red[tid * 2] + red[tid * 2 + 1] + sb3[0];
        int i = bx * 8 + (tid >> 3), j = by * 8 + (tid & 7);
        if (i < j) {
            out[i * 512 + j] = s;
            out[j * 512 + i] = s;
        } else if (i == j) {
            out[i * 512 + j] = 0.f;
        }
    }
}

// ---------------- launch (R14 structure) ----------------
extern "C" void kernel_launch(void* const* d_in, const int* in_sizes, int n_in,
                              void* d_out, int out_size) {
    const float *x = 0, *node_W = 0, *node_b = 0, *gat_W = 0, *att_src = 0,
                *att_dst = 0, *gat_b = 0, *ln_g = 0, *ln_b = 0, *sW1 = 0,
                *sb1 = 0, *sW2 = 0, *sb2 = 0, *sW3 = 0, *sb3 = 0;
    const int *edge_index = 0, *odd = 0;
    int c1536 = 0, c384 = 0, c128 = 0;
    for (int i = 0; i < n_in; i++) {
        const void* p = d_in[i];
        switch (in_sizes[i]) {
            case 100000: x = (const float*)p; break;
            case 640000: edge_index = (const int*)p; break;
            case 512:    odd = (const int*)p; break;
            case 640:    node_W = (const float*)p; break;
            case 196608: gat_W = (const float*)p; break;
            case 1536:   if (c1536++ == 0) att_src = (const float*)p; else att_dst = (const float*)p; break;
            case 384:    if (c384 == 0) gat_b = (const float*)p;
                         else if (c384 == 1) ln_g = (const float*)p;
                         else ln_b = (const float*)p;
                         c384++; break;
            case 32768:  sW1 = (const float*)p; break;
            case 16384:  sW2 = (const float*)p; break;
            case 128:    if (c128 == 0) node_b = (const float*)p;
                         else if (c128 == 1) sb1 = (const float*)p;
                         else if (c128 == 2) sb2 = (const float*)p;
                         else sW3 = (const float*)p;
                         c128++; break;
            case 1:      sb3 = (const float*)p; break;
            default: break;
        }
    }
    float* outp = (float*)d_out;

    const int GEMM_SMEM = (64 + 128) * SPC * 2;                    // 27648 B
    const int PAIR_SMEM = (2 * 64 + 2 * 128) * SPC * 2;            // 55296 B
    cudaFuncSetAttribute(k_gemm_att, cudaFuncAttributeMaxDynamicSharedMemorySize, GEMM_SMEM);
    cudaFuncSetAttribute(k_pair_mma, cudaFuncAttributeMaxDynamicSharedMemorySize, PAIR_SMEM);

    // fork-join: CSR chain on side stream, overlapped with gemm layer-0
    cudaStream_t sb;
    cudaStreamCreateWithFlags(&sb, cudaStreamNonBlocking);
    cudaEvent_t ev0, ev1;
    cudaEventCreateWithFlags(&ev0, cudaEventDisableTiming);
    cudaEventCreateWithFlags(&ev1, cudaEventDisableTiming);

    k_prologue<<<PRO_GRID, 128>>>(gat_W, sW2, x, node_W, node_b);
    cudaEventRecord(ev0, 0);

    cudaStreamWaitEvent(sb, ev0, 0);
    k_hist<<<(ETOT + 255) / 256, 256, 0, sb>>>(edge_index);
    k_blksum<<<NB, 128, 0, sb>>>();
    k_blkscan<<<1, 160, 0, sb>>>();
    k_apply<<<NB, 128, 0, sb>>>();
    k_scatter<<<(ETOT + 255) / 256, 256, 0, sb>>>(edge_index);
    cudaEventRecord(ev1, sb);

    k_gemm_att<<<dim3(313, 4), 128, GEMM_SMEM>>>(0, att_src, att_dst);
    cudaStreamWaitEvent(0, ev1, 0);
    k_fused<<<(NN + 7) / 8, 256>>>(0, gat_b, ln_g, ln_b);

    for (int l = 1; l < NLAYERS; l++) {
        k_gemm_att<<<dim3(313, 4), 128, GEMM_SMEM>>>(l, att_src + l * 512, att_dst + l * 512);
        k_fused<<<(NN + 7) / 8, 256>>>(l, gat_b + l * 128, ln_g + l * 128, ln_b + l * 128);
    }

    k_pq<<<NODD, 128>>>(odd, sW1, sb1);
    k_pair_mma<<<2080, 128, PAIR_SMEM>>>(sb2, sW3, sb3, outp);

    cudaEventDestroy(ev0);
    cudaEventDestroy(ev1);
    cudaStreamDestroy(sb);
}

// round 16
// speedup vs baseline: 1.7550x; 1.0655x over previous
#include <cuda_runtime.h>
#include <cuda_bf16.h>
#include <cuda_fp16.h>
#include <cstdint>

#define NN 20000
#define EE 320000
#define ETOT 340000   // EE + NN self loops
#define NODD 512
#define HIDD 128
#define NLAYERS 3
#define SPC 72        // padded 16-bit smem row stride (k=64 chunks)
#define NB 157        // ceil(NN/128)

// ---------------- static scratch ----------------
__device__ float d_h[NN * HIDD];
__device__ __half d_hf[NN * HIDD];          // h in fp16 (gemm A operand)
__device__ __half d_zh[NN * 512];           // z in fp16
__device__ float d_es[NLAYERS * NN * 4];    // per-layer (zeroed once)
__device__ float d_ed[NLAYERS * NN * 4];
__device__ int   d_cnt[NN];
__device__ int   d_cur[NN];
__device__ int   d_off[NN + 1];
__device__ int   d_csr[ETOT];
__device__ int   d_blk[NB + 8];
__device__ float d_P[NODD * HIDD];
__device__ float d_Q[NODD * HIDD];
__device__ __half d_wtf[NLAYERS * 512 * 128];            // gat_W transposed fp16 [l][n][k]
__device__ __nv_bfloat16 d_w2t_hi[128 * 128];            // sW2 transposed (pair: bf16x3)
__device__ __nv_bfloat16 d_w2t_lo[128 * 128];

__device__ __forceinline__ void bsplit(float v, __nv_bfloat16& hi, __nv_bfloat16& lo) {
    hi = __float2bfloat16(v);
    lo = __float2bfloat16(v - __bfloat162float(hi));
}

__device__ __forceinline__ void mma_bf16(float* c, uint32_t a0, uint32_t a1, uint32_t a2,
                                         uint32_t a3, uint32_t b0, uint32_t b1) {
    asm volatile(
        "mma.sync.aligned.m16n8k16.row.col.f32.bf16.bf16.f32 "
        "{%0,%1,%2,%3}, {%4,%5,%6,%7}, {%8,%9}, {%0,%1,%2,%3};\n"
        : "+f"(c[0]), "+f"(c[1]), "+f"(c[2]), "+f"(c[3])
        : "r"(a0), "r"(a1), "r"(a2), "r"(a3), "r"(b0), "r"(b1));
}

__device__ __forceinline__ void mma_f16(float* c, uint32_t a0, uint32_t a1, uint32_t a2,
                                        uint32_t a3, uint32_t b0, uint32_t b1) {
    asm volatile(
        "mma.sync.aligned.m16n8k16.row.col.f32.f16.f16.f32 "
        "{%0,%1,%2,%3}, {%4,%5,%6,%7}, {%8,%9}, {%0,%1,%2,%3};\n"
        : "+f"(c[0]), "+f"(c[1]), "+f"(c[2]), "+f"(c[3])
        : "r"(a0), "r"(a1), "r"(a2), "r"(a3), "r"(b0), "r"(b1));
}

__device__ __forceinline__ void ldmA(uint32_t* a, uint32_t saddr) {
    asm volatile("ldmatrix.sync.aligned.m8n8.x4.shared.b16 {%0,%1,%2,%3}, [%4];"
                 : "=r"(a[0]), "=r"(a[1]), "=r"(a[2]), "=r"(a[3]) : "r"(saddr));
}
__device__ __forceinline__ void ldmB2(uint32_t& b0, uint32_t& b1, uint32_t saddr) {
    asm volatile("ldmatrix.sync.aligned.m8n8.x2.shared.b16 {%0,%1}, [%2];"
                 : "=r"(b0), "=r"(b1) : "r"(saddr));
}

// ---------------- prologue: prep_w + prep_w2 + node_proj + all zeroing ----------------
#define PRO_W   1536
#define PRO_W2  128
#define PRO_NP  20000
#define PRO_Z   1875
#define PRO_GRID (PRO_W + PRO_W2 + PRO_NP + PRO_Z)

__global__ void k_prologue(const float* __restrict__ gw,
                           const float* __restrict__ w2,
                           const float* __restrict__ x,
                           const float* __restrict__ nW,
                           const float* __restrict__ nb) {
    int b = blockIdx.x, t = threadIdx.x;
    if (b < PRO_W) {
        int l = b >> 9, n = b & 511;
        d_wtf[(l * 512 + n) * 128 + t] = __float2half(gw[(l * 128 + t) * 512 + n]);
    } else if (b < PRO_W + PRO_W2) {
        int n = b - PRO_W;
        float v = w2[t * 128 + n];
        __nv_bfloat16 hi, lo; bsplit(v, hi, lo);
        d_w2t_hi[n * 128 + t] = hi;
        d_w2t_lo[n * 128 + t] = lo;
    } else if (b < PRO_W + PRO_W2 + PRO_NP) {
        int n = b - PRO_W - PRO_W2;
        float acc = nb[t];
#pragma unroll
        for (int k = 0; k < 5; k++) acc += x[n * 5 + k] * nW[k * HIDD + t];
        acc = fmaxf(acc, 0.f);
        d_h[n * HIDD + t] = acc;
        d_hf[n * HIDD + t] = __float2half(acc);
    } else {
        int i = (b - PRO_W - PRO_W2 - PRO_NP) * 128 + t;
        if (i < NN) d_cnt[i] = 0;
        if (i < NLAYERS * NN * 4) { d_es[i] = 0.f; d_ed[i] = 0.f; }
    }
}

// ---------------- CSR build ----------------
__global__ void k_hist(const int* __restrict__ ei) {
    int e = blockIdx.x * blockDim.x + threadIdx.x;
    if (e >= ETOT) return;
    int d = (e < EE) ? ei[EE + e] : (e - EE);
    atomicAdd(&d_cnt[d], 1);
}
__global__ void k_blksum() {
    int b = blockIdx.x, t = threadIdx.x, i = b * 128 + t;
    int v = (i < NN) ? d_cnt[i] : 0;
#pragma unroll
    for (int o = 16; o; o >>= 1) v += __shfl_xor_sync(0xffffffffu, v, o);
    __shared__ int ws[4];
    if ((t & 31) == 0) ws[t >> 5] = v;
    __syncthreads();
    if (t == 0) d_blk[b] = ws[0] + ws[1] + ws[2] + ws[3];
}
__global__ void k_blkscan() {   // 160 threads
    int t = threadIdx.x, lane = t & 31, w = t >> 5;
    int v = (t < NB) ? d_blk[t] : 0;
    int x = v;
#pragma unroll
    for (int o = 1; o < 32; o <<= 1) {
        int y = __shfl_up_sync(0xffffffffu, x, o);
        if (lane >= o) x += y;
    }
    __shared__ int ws[5];
    if (lane == 31) ws[w] = x;
    __syncthreads();
    int add = 0;
    for (int q = 0; q < w; q++) add += ws[q];
    if (t < NB) d_blk[t] = x - v + add;
}
__global__ void k_apply() {
    int b = blockIdx.x, t = threadIdx.x, i = b * 128 + t;
    int lane = t & 31, w = t >> 5;
    int v = (i < NN) ? d_cnt[i] : 0;
    int x = v;
#pragma unroll
    for (int o = 1; o < 32; o <<= 1) {
        int y = __shfl_up_sync(0xffffffffu, x, o);
        if (lane >= o) x += y;
    }
    __shared__ int ws[4];
    if (lane == 31) ws[w] = x;
    __syncthreads();
    int add = 0;
    for (int q = 0; q < w; q++) add += ws[q];
    int ex = x - v + add + d_blk[b];
    if (i < NN) { d_off[i] = ex; d_cur[i] = ex; }
    if (i == 0) d_off[NN] = ETOT;
}
__global__ void k_scatter(const int* __restrict__ ei) {
    int e = blockIdx.x * blockDim.x + threadIdx.x;
    if (e >= ETOT) return;
    int d, s;
    if (e < EE) { s = ei[e]; d = ei[EE + e]; }
    else        { s = e - EE; d = e - EE; }
    int pos = atomicAdd(&d_cur[d], 1);
    d_csr[pos] = s;
}

// ---------------- z = h @ W via fp16 mma (ldmatrix), BN=128 tile, one head/block ----
__global__ void __launch_bounds__(128) k_gemm_att(int l,
                                                  const float* __restrict__ asrc,
                                                  const float* __restrict__ adst) {
    extern __shared__ __half smh[];
    __half* AH = smh;                 // 64 x SPC (chunk)
    __half* WH = smh + 64 * SPC;      // 128 x SPC (chunk)

    int tid = threadIdx.x;
    int bm = blockIdx.x * 64;
    int h = blockIdx.y;
    int bn = h << 7;

    int wid = tid >> 5, lane = tid & 31;
    int g = lane >> 2, tig = lane & 3;
    int wm = (wid & 1) * 32, wn = (wid >> 1) * 64;

    uint32_t AHs = (uint32_t)__cvta_generic_to_shared(AH);
    uint32_t WHs = (uint32_t)__cvta_generic_to_shared(WH);

    int q = lane >> 3, rr = lane & 7;
    int a_row = (q & 1) * 8 + rr;
    int a_col = (q >> 1) * 8;
    int b_ko = ((lane >> 3) & 1) * 8;

    float c[2][8][4] = {};

    for (int kc = 0; kc < 128; kc += 64) {
        if (kc) __syncthreads();
#pragma unroll
        for (int i = 0; i < 4; i++) {
            int u = i * 128 + tid;
            int r = u >> 3, c8 = (u & 7) * 8;
            uint4 vh = make_uint4(0u, 0u, 0u, 0u);
            if (bm + r < NN)
                vh = *(const uint4*)&d_hf[(bm + r) * 128 + kc + c8];
            *(uint4*)&AH[r * SPC + c8] = vh;
        }
#pragma unroll
        for (int i = 0; i < 8; i++) {
            int u = i * 128 + tid;
            int n = u >> 3, k8 = (u & 7) * 8;
            *(uint4*)&WH[n * SPC + k8] = *(const uint4*)&d_wtf[(l * 512 + bn + n) * 128 + kc + k8];
        }
        __syncthreads();

#pragma unroll
        for (int ks = 0; ks < 4; ks++) {
            uint32_t a[2][4];
#pragma unroll
            for (int mt = 0; mt < 2; mt++)
                ldmA(a[mt], AHs + ((wm + mt * 16 + a_row) * SPC + ks * 16 + a_col) * 2);
#pragma unroll
            for (int nt = 0; nt < 8; nt++) {
                uint32_t b0, b1;
                ldmB2(b0, b1, WHs + ((wn + nt * 8 + rr) * SPC + ks * 16 + b_ko) * 2);
#pragma unroll
                for (int mt = 0; mt < 2; mt++)
                    mma_f16(c[mt][nt], a[mt][0], a[mt][1], a[mt][2], a[mt][3], b0, b1);
            }
        }
    }

#pragma unroll
    for (int mt = 0; mt < 2; mt++) {
        int r0 = bm + wm + mt * 16 + g;
#pragma unroll
        for (int nt = 0; nt < 8; nt++) {
            int col = bn + wn + nt * 8 + 2 * tig;
            if (r0 < NN)
                *(__half2*)&d_zh[r0 * 512 + col] =
                    __float22half2_rn(make_float2(c[mt][nt][0], c[mt][nt][1]));
            if (r0 + 8 < NN)
                *(__half2*)&d_zh[(r0 + 8) * 512 + col] =
                    __float22half2_rn(make_float2(c[mt][nt][2], c[mt][nt][3]));
        }
    }

    float* esb = &d_es[l * NN * 4];
    float* edb = &d_ed[l * NN * 4];
    float ps[2][2] = {}, pd[2][2] = {};
#pragma unroll
    for (int mt = 0; mt < 2; mt++) {
#pragma unroll
        for (int nt = 0; nt < 8; nt++) {
            int cih = wn + nt * 8 + 2 * tig;
            float a0 = asrc[h * 128 + cih], a1 = asrc[h * 128 + cih + 1];
            float d0 = adst[h * 128 + cih], d1 = adst[h * 128 + cih + 1];
            ps[mt][0] += c[mt][nt][0] * a0 + c[mt][nt][1] * a1;
            pd[mt][0] += c[mt][nt][0] * d0 + c[mt][nt][1] * d1;
            ps[mt][1] += c[mt][nt][2] * a0 + c[mt][nt][3] * a1;
            pd[mt][1] += c[mt][nt][2] * d0 + c[mt][nt][3] * d1;
        }
    }
#pragma unroll
    for (int o = 1; o < 4; o <<= 1) {
#pragma unroll
        for (int mt = 0; mt < 2; mt++) {
#pragma unroll
            for (int rh = 0; rh < 2; rh++) {
                ps[mt][rh] += __shfl_xor_sync(0xffffffffu, ps[mt][rh], o);
                pd[mt][rh] += __shfl_xor_sync(0xffffffffu, pd[mt][rh], o);
            }
        }
    }
    if (tig == 0) {
#pragma unroll
        for (int mt = 0; mt < 2; mt++) {
#pragma unroll
            for (int rh = 0; rh < 2; rh++) {
                int r = bm + wm + mt * 16 + g + rh * 8;
                if (r < NN) {
                    atomicAdd(&esb[r * 4 + h], ps[mt][rh]);
                    atomicAdd(&edb[r * 4 + h], pd[mt][rh]);
                }
            }
        }
    }
}

// ---------------- fused softmax-aggregate + head-mean + LN + relu + residual ----
// Lane L owns 8 dims ((L&15)*8) of 2 heads (parity L>>4): per edge 2x uint4 z
// loads (was 4x uint2) and 2 expf (was 4). Head-mean via shfl_xor(...,16).
__global__ void k_fused(int l,
                        const float* __restrict__ gb,
                        const float* __restrict__ lg,
                        const float* __restrict__ lb) {
    int wid = threadIdx.x >> 5, lane = threadIdx.x & 31;
    int n = blockIdx.x * 8 + wid;
    if (n >= NN) return;

    const float* esb = &d_es[l * NN * 4];
    const float* edb = &d_ed[l * NN * 4];

    int hlo = lane >> 4;              // head parity: heads {hlo, hlo+2}
    int dL = (lane & 15) * 8;         // dim base (8 dims)
    int offA = hlo * 128 + dL;        // head hlo
    int offB = 256 + hlo * 128 + dL;  // head hlo+2

    float4 ed4 = *(const float4*)&edb[n * 4];
    float edvA = hlo ? ed4.y : ed4.x;
    float edvB = hlo ? ed4.w : ed4.z;

    float sdenA = 0.f, sdenB = 0.f;
    float accA[8] = {}, accB[8] = {};

#define EDGE_BODY(sidx)                                                         \
    {                                                                           \
        int s_ = (sidx);                                                        \
        float4 es4 = *(const float4*)&esb[s_ * 4];                              \
        uint4 za = *(const uint4*)&d_zh[s_ * 512 + offA];                       \
        uint4 zb = *(const uint4*)&d_zh[s_ * 512 + offB];                       \
        float eA = (hlo ? es4.y : es4.x) + edvA;                                \
        float eB = (hlo ? es4.w : es4.z) + edvB;                                \
        eA = (eA > 0.f) ? eA : 0.2f * eA;                                       \
        eB = (eB > 0.f) ? eB : 0.2f * eB;                                       \
        float pA = __expf(eA), pB = __expf(eB);                                 \
        sdenA += pA; sdenB += pB;                                               \
        float2 a0 = __half22float2(*(const __half2*)&za.x);                     \
        float2 a1 = __half22float2(*(const __half2*)&za.y);                     \
        float2 a2 = __half22float2(*(const __half2*)&za.z);                     \
        float2 a3 = __half22float2(*(const __half2*)&za.w);                     \
        accA[0] += pA * a0.x; accA[1] += pA * a0.y;                             \
        accA[2] += pA * a1.x; accA[3] += pA * a1.y;                             \
        accA[4] += pA * a2.x; accA[5] += pA * a2.y;                             \
        accA[6] += pA * a3.x; accA[7] += pA * a3.y;                             \
        float2 b0 = __half22float2(*(const __half2*)&zb.x);                     \
        float2 b1 = __half22float2(*(const __half2*)&zb.y);                     \
        float2 b2 = __half22float2(*(const __half2*)&zb.z);                     \
        float2 b3 = __half22float2(*(const __half2*)&zb.w);                     \
        accB[0] += pB * b0.x; accB[1] += pB * b0.y;                             \
        accB[2] += pB * b1.x; accB[3] += pB * b1.y;                             \
        accB[4] += pB * b2.x; accB[5] += pB * b2.y;                             \
        accB[6] += pB * b3.x; accB[7] += pB * b3.y;                             \
    }

    int beg = d_off[n], end = d_off[n + 1];
    int e = beg;
    for (; e + 1 < end; e += 2) {
        int s0 = d_csr[e];
        int s1 = d_csr[e + 1];
        EDGE_BODY(s0);
        EDGE_BODY(s1);
    }
    if (e < end) EDGE_BODY(d_csr[e]);
#undef EDGE_BODY

    // r[d] = heads {hlo, hlo+2} mean-part for dims dL..dL+7
    float invA = 1.f / sdenA, invB = 1.f / sdenB;
    float r[8];
#pragma unroll
    for (int d = 0; d < 8; d++)
        r[d] = accA[d] * invA + accB[d] * invB;
    // combine with opposite head parity (lane ^ 16 owns same dims, other heads)
#pragma unroll
    for (int d = 0; d < 8; d++) {
        float oth = __shfl_xor_sync(0xffffffffu, r[d], 16);
        r[d] = 0.25f * (r[d] + oth) + gb[dL + d];
    }

    // layernorm: warp sum double-counts every dim (lanes L and L^16 identical)
    float s1 = 0.f, s2 = 0.f;
#pragma unroll
    for (int d = 0; d < 8; d++) { s1 += r[d]; s2 += r[d] * r[d]; }
#pragma unroll
    for (int o = 16; o > 0; o >>= 1) {
        s1 += __shfl_xor_sync(0xffffffffu, s1, o);
        s2 += __shfl_xor_sync(0xffffffffu, s2, o);
    }
    float mu = s1 * (1.f / 256.f);
    float var = s2 * (1.f / 256.f) - mu * mu;
    float rstd = rsqrtf(var + 1e-5f);

    if (hlo == 0) {   // lanes 0-15 write dims dL..dL+7
        float4 h0 = *(const float4*)&d_h[n * 128 + dL];
        float4 h1 = *(const float4*)&d_h[n * 128 + dL + 4];
        float hold[8] = {h0.x, h0.y, h0.z, h0.w, h1.x, h1.y, h1.z, h1.w};
        float outv[8];
        __half oh[8];
#pragma unroll
        for (int d = 0; d < 8; d++) {
            float v = (r[d] - mu) * rstd * lg[dL + d] + lb[dL + d];
            outv[d] = fmaxf(v, 0.f) + hold[d];
            oh[d] = __float2half(outv[d]);
        }
        *(float4*)&d_h[n * 128 + dL]     = make_float4(outv[0], outv[1], outv[2], outv[3]);
        *(float4*)&d_h[n * 128 + dL + 4] = make_float4(outv[4], outv[5], outv[6], outv[7]);
        *(uint4*)&d_hf[n * 128 + dL] = *(uint4*)oh;
    }
}

// ---------------- P/Q for pair MLP layer 1 ----------------
__global__ void k_pq(const int* __restrict__ odd,
                     const float* __restrict__ sW1,
                     const float* __restrict__ sb1) {
    int i = blockIdx.x, c = threadIdx.x;
    __shared__ float hs[128];
    hs[c] = d_h[odd[i] * 128 + c];
    __syncthreads();
    float p = sb1[c], q = 0.f;
#pragma unroll 8
    for (int k = 0; k < 128; k++) {
        float hk = hs[k];
        p += hk * sW1[k * 128 + c];
        q += hk * sW1[(128 + k) * 128 + c];
    }
    d_P[i * 128 + c] = p;
    d_Q[i * 128 + c] = q;
}

// ---------------- pair scoring: bf16x3 mma (ldmatrix), A+W both k-chunked ----------
__global__ void __launch_bounds__(128) k_pair_mma(const float* __restrict__ sb2,
                                                  const float* __restrict__ sW3,
                                                  const float* __restrict__ sb3,
                                                  float* __restrict__ out) {
    int t = blockIdx.x;
    int bx = (int)((129.0f - sqrtf(16641.0f - 8.0f * (float)t)) * 0.5f);
    if (bx > 63) bx = 63;
    while (bx > 0 && 64 * bx - (bx * (bx - 1)) / 2 > t) bx--;
    while (64 * (bx + 1) - ((bx + 1) * bx) / 2 <= t) bx++;
    int by = bx + (t - (64 * bx - (bx * (bx - 1)) / 2));

    extern __shared__ __nv_bfloat16 smb[];
    __nv_bfloat16* AH = smb;
    __nv_bfloat16* AL = smb + 64 * SPC;
    __nv_bfloat16* WH = smb + 2 * 64 * SPC;
    __nv_bfloat16* WL = smb + 2 * 64 * SPC + 128 * SPC;

    int tid = threadIdx.x;
    int wid = tid >> 5, lane = tid & 31;
    int g = lane >> 2, tig = lane & 3;
    int wm = (wid & 1) * 32, wn = (wid >> 1) * 64;

    uint32_t AHs = (uint32_t)__cvta_generic_to_shared(AH);
    uint32_t ALs = (uint32_t)__cvta_generic_to_shared(AL);
    uint32_t WHs = (uint32_t)__cvta_generic_to_shared(WH);
    uint32_t WLs = (uint32_t)__cvta_generic_to_shared(WL);

    int q = lane >> 3, rr = lane & 7;
    int a_row = (q & 1) * 8 + rr;
    int a_col = (q >> 1) * 8;
    int b_ko = ((lane >> 3) & 1) * 8;

    int kk = tid & 63;
    int half = tid >> 6;

    float c[2][8][4] = {};

    for (int kc = 0; kc < 128; kc += 64) {
        if (kc) __syncthreads();
        {
            float p4[4], q8[8];
#pragma unroll
            for (int r = 0; r < 4; r++)
                p4[r] = d_P[(bx * 8 + half * 4 + r) * 128 + kc + kk];
#pragma unroll
            for (int cc = 0; cc < 8; cc++)
                q8[cc] = d_Q[(by * 8 + cc) * 128 + kc + kk];
#pragma unroll
            for (int r = 0; r < 4; r++) {
#pragma unroll
                for (int cc = 0; cc < 8; cc++) {
                    float v = fmaxf(p4[r] + q8[cc], 0.f);
                    __nv_bfloat16 hi, lo; bsplit(v, hi, lo);
                    int p = (half * 4 + r) * 8 + cc;
                    AH[p * SPC + kk] = hi;
                    AL[p * SPC + kk] = lo;
                }
            }
        }
#pragma unroll
        for (int i = 0; i < 8; i++) {
            int u = i * 128 + tid;
            int n = u >> 3, k8 = (u & 7) * 8;
            *(uint4*)&WH[n * SPC + k8] = *(const uint4*)&d_w2t_hi[n * 128 + kc + k8];
            *(uint4*)&WL[n * SPC + k8] = *(const uint4*)&d_w2t_lo[n * 128 + kc + k8];
        }
        __syncthreads();

#pragma unroll
        for (int ks = 0; ks < 4; ks++) {
            uint32_t aH[2][4], aL[2][4];
#pragma unroll
            for (int mt = 0; mt < 2; mt++) {
                ldmA(aH[mt], AHs + ((wm + mt * 16 + a_row) * SPC + ks * 16 + a_col) * 2);
                ldmA(aL[mt], ALs + ((wm + mt * 16 + a_row) * SPC + ks * 16 + a_col) * 2);
            }
#pragma unroll
            for (int nt = 0; nt < 8; nt++) {
                uint32_t bH0, bH1, bL0, bL1;
                ldmB2(bH0, bH1, WHs + ((wn + nt * 8 + rr) * SPC + ks * 16 + b_ko) * 2);
                ldmB2(bL0, bL1, WLs + ((wn + nt * 8 + rr) * SPC + ks * 16 + b_ko) * 2);
#pragma unroll
                for (int mt = 0; mt < 2; mt++) {
                    mma_bf16(c[mt][nt], aH[mt][0], aH[mt][1], aH[mt][2], aH[mt][3], bH0, bH1);
                    mma_bf16(c[mt][nt], aH[mt][0], aH[mt][1], aH[mt][2], aH[mt][3], bL0, bL1);
                    mma_bf16(c[mt][nt], aL[mt][0], aL[mt][1], aL[mt][2], aL[mt][3], bH0, bH1);
                }
            }
        }
    }
    __syncthreads();

    float* red = (float*)smb;
#pragma unroll
    for (int mt = 0; mt < 2; mt++) {
        float p0 = 0.f, p1 = 0.f;
#pragma unroll
        for (int nt = 0; nt < 8; nt++) {
            int c0 = wn + nt * 8 + 2 * tig;
            float w30 = sW3[c0], w31 = sW3[c0 + 1];
            float bb0 = sb2[c0], bb1 = sb2[c0 + 1];
            p0 += fmaxf(c[mt][nt][0] + bb0, 0.f) * w30 + fmaxf(c[mt][nt][1] + bb1, 0.f) * w31;
            p1 += fmaxf(c[mt][nt][2] + bb0, 0.f) * w30 + fmaxf(c[mt][nt][3] + bb1, 0.f) * w31;
        }
#pragma unroll
        for (int o = 1; o < 4; o <<= 1) {
            p0 += __shfl_xor_sync(0xffffffffu, p0, o);
            p1 += __shfl_xor_sync(0xffffffffu, p1, o);
        }
        if (tig == 0) {
            int r = wm + mt * 16 + g;
            red[r * 2 + (wid >> 1)] = p0;
            red[(r + 8) * 2 + (wid >> 1)] = p1;
        }
    }
    __syncthreads();
    if (tid < 64) {
        float s = red[tid * 2] + red[tid * 2 + 1] + sb3[0];
        int i = bx * 8 + (tid >> 3), j = by * 8 + (tid & 7);
        if (i < j) {
            out[i * 512 + j] = s;
            out[j * 512 + i] = s;
        } else if (i == j) {
            out[i * 512 + j] = 0.f;
        }
    }
}

// ---------------- launch (R15 structure) ----------------
extern "C" void kernel_launch(void* const* d_in, const int* in_sizes, int n_in,
                              void* d_out, int out_size) {
    const float *x = 0, *node_W = 0, *node_b = 0, *gat_W = 0, *att_src = 0,
                *att_dst = 0, *gat_b = 0, *ln_g = 0, *ln_b = 0, *sW1 = 0,
                *sb1 = 0, *sW2 = 0, *sb2 = 0, *sW3 = 0, *sb3 = 0;
    const int *edge_index = 0, *odd = 0;
    int c1536 = 0, c384 = 0, c128 = 0;
    for (int i = 0; i < n_in; i++) {
        const void* p = d_in[i];
        switch (in_sizes[i]) {
            case 100000: x = (const float*)p; break;
            case 640000: edge_index = (const int*)p; break;
            case 512:    odd = (const int*)p; break;
            case 640:    node_W = (const float*)p; break;
            case 196608: gat_W = (const float*)p; break;
            case 1536:   if (c1536++ == 0) att_src = (const float*)p; else att_dst = (const float*)p; break;
            case 384:    if (c384 == 0) gat_b = (const float*)p;
                         else if (c384 == 1) ln_g = (const float*)p;
                         else ln_b = (const float*)p;
                         c384++; break;
            case 32768:  sW1 = (const float*)p; break;
            case 16384:  sW2 = (const float*)p; break;
            case 128:    if (c128 == 0) node_b = (const float*)p;
                         else if (c128 == 1) sb1 = (const float*)p;
                         else if (c128 == 2) sb2 = (const float*)p;
                         else sW3 = (const float*)p;
                         c128++; break;
            case 1:      sb3 = (const float*)p; break;
            default: break;
        }
    }
    float* outp = (float*)d_out;

    const int GEMM_SMEM = (64 + 128) * SPC * 2;                    // 27648 B
    const int PAIR_SMEM = (2 * 64 + 2 * 128) * SPC * 2;            // 55296 B
    cudaFuncSetAttribute(k_gemm_att, cudaFuncAttributeMaxDynamicSharedMemorySize, GEMM_SMEM);
    cudaFuncSetAttribute(k_pair_mma, cudaFuncAttributeMaxDynamicSharedMemorySize, PAIR_SMEM);

    cudaStream_t sb;
    cudaStreamCreateWithFlags(&sb, cudaStreamNonBlocking);
    cudaEvent_t ev0, ev1;
    cudaEventCreateWithFlags(&ev0, cudaEventDisableTiming);
    cudaEventCreateWithFlags(&ev1, cudaEventDisableTiming);

    k_prologue<<<PRO_GRID, 128>>>(gat_W, sW2, x, node_W, node_b);
    cudaEventRecord(ev0, 0);

    cudaStreamWaitEvent(sb, ev0, 0);
    k_hist<<<(ETOT + 255) / 256, 256, 0, sb>>>(edge_index);
    k_blksum<<<NB, 128, 0, sb>>>();
    k_blkscan<<<1, 160, 0, sb>>>();
    k_apply<<<NB, 128, 0, sb>>>();
    k_scatter<<<(ETOT + 255) / 256, 256, 0, sb>>>(edge_index);
    cudaEventRecord(ev1, sb);

    k_gemm_att<<<dim3(313, 4), 128, GEMM_SMEM>>>(0, att_src, att_dst);
    cudaStreamWaitEvent(0, ev1, 0);
    k_fused<<<(NN + 7) / 8, 256>>>(0, gat_b, ln_g, ln_b);

    for (int l = 1; l < NLAYERS; l++) {
        k_gemm_att<<<dim3(313, 4), 128, GEMM_SMEM>>>(l, att_src + l * 512, att_dst + l * 512);
        k_fused<<<(NN + 7) / 8, 256>>>(l, gat_b + l * 128, ln_g + l * 128, ln_b + l * 128);
    }

    k_pq<<<NODD, 128>>>(odd, sW1, sb1);
    k_pair_mma<<<2080, 128, PAIR_SMEM>>>(sb2, sW3, sb3, outp);

    cudaEventDestroy(ev0);
    cudaEventDestroy(ev1);
    cudaStreamDestroy(sb);
}